// round 1
// baseline (speedup 1.0000x reference)
#include <cuda_runtime.h>
#include <math.h>

#define B_   4
#define S_   4096
#define D_   512
#define H_   8
#define KD_  64
#define R_   256
#define M_   (B_*S_)       // 16384 rows of x
#define ROWS_ (M_*H_)      // 131072 (b,s,h) rows
#define EPS_ 1e-3f
#define SCALE_ 0.125f      // 1/sqrt(64)
#define NSPLIT 16

// ---------------- scratch (static device globals; no runtime allocation) ----------------
__device__ float g_q[M_*D_];
__device__ float g_k[M_*D_];
__device__ float g_v[M_*D_];
__device__ float g_qf[(size_t)ROWS_*R_];      // 128 MB
__device__ float g_kf[(size_t)ROWS_*R_];      // 128 MB
__device__ float g_kvp[B_*H_*NSPLIT*R_*KD_];  // split partials
__device__ float g_ksump[B_*H_*NSPLIT*R_];
__device__ float g_kv[B_*H_*R_*KD_];
__device__ float g_ksum[B_*H_*R_];
__device__ float g_attn[M_*D_];

// ---------------- generic fp32 GEMM: C[M,N] = A[M,K] @ B[K,N] (+bias) ----------------
// BM=BN=64, BK=16, 256 threads, 4x4 microtile.
__global__ void gemm64(const float* __restrict__ A, const float* __restrict__ Bm,
                       float* __restrict__ C, const float* __restrict__ bias,
                       int M, int N, int K) {
    __shared__ float As[16][64];
    __shared__ float Bs[16][64];
    int bx = blockIdx.x, by = blockIdx.y;
    int t = threadIdx.x;
    int tx = t & 15, ty = t >> 4;
    float acc[4][4] = {};
    int arow = t >> 2, ac = t & 3;     // A tile: 64 rows x 4 float4 cols
    int brow = t >> 4, bc = t & 15;    // B tile: 16 rows x 16 float4 cols
    const float* Ap = A + (size_t)(by*64 + arow)*K + ac*4;
    const float* Bp = Bm + (size_t)brow*N + bx*64 + bc*4;

    for (int kb = 0; kb < K; kb += 16) {
        float4 a4 = *(const float4*)(Ap + kb);
        float4 b4 = *(const float4*)(Bp + (size_t)kb*N);
        As[ac*4+0][arow] = a4.x;
        As[ac*4+1][arow] = a4.y;
        As[ac*4+2][arow] = a4.z;
        As[ac*4+3][arow] = a4.w;
        *(float4*)&Bs[brow][bc*4] = b4;
        __syncthreads();
        #pragma unroll
        for (int k = 0; k < 16; k++) {
            float4 af = *(float4*)&As[k][ty*4];
            float4 bf = *(float4*)&Bs[k][tx*4];
            acc[0][0] += af.x*bf.x; acc[0][1] += af.x*bf.y; acc[0][2] += af.x*bf.z; acc[0][3] += af.x*bf.w;
            acc[1][0] += af.y*bf.x; acc[1][1] += af.y*bf.y; acc[1][2] += af.y*bf.z; acc[1][3] += af.y*bf.w;
            acc[2][0] += af.z*bf.x; acc[2][1] += af.z*bf.y; acc[2][2] += af.z*bf.z; acc[2][3] += af.z*bf.w;
            acc[3][0] += af.w*bf.x; acc[3][1] += af.w*bf.y; acc[3][2] += af.w*bf.z; acc[3][3] += af.w*bf.w;
        }
        __syncthreads();
    }
    int col = bx*64 + tx*4;
    float4 bb = bias ? *(const float4*)(bias + col) : make_float4(0.f,0.f,0.f,0.f);
    #pragma unroll
    for (int i = 0; i < 4; i++) {
        int row = by*64 + ty*4 + i;
        float4 o = make_float4(acc[i][0]+bb.x, acc[i][1]+bb.y, acc[i][2]+bb.z, acc[i][3]+bb.w);
        *(float4*)(C + (size_t)row*N + col) = o;
    }
}

// ---------------- feature kernel: proj = row . rf^T * SCALE; exp(proj - rowmax) + EPS ----
// rf transposed into dynamic smem rfT[64][256] -> conflict-free LDS.128.
// warp per row; lane handles r in [lane*8, lane*8+8).
__global__ void feat_kernel(const float* __restrict__ T, const float* __restrict__ rf,
                            float* __restrict__ outF) {
    extern __shared__ float sm[];
    float* rfT = sm;                       // 64*256 floats
    int t = threadIdx.x;
    int warp = t >> 5, lane = t & 31;
    float* qs = sm + 64*256 + warp*64;     // per-warp row buffer

    for (int i = t; i < R_*KD_; i += 256) {
        int r = i >> 6, d = i & 63;
        rfT[d*R_ + r] = rf[i];
    }
    __syncthreads();

    int row0 = blockIdx.x*128 + warp*16;
    const float* rbase = rfT + lane*8;
    for (int rr = 0; rr < 16; rr++) {
        size_t m = (size_t)row0 + rr;
        if (lane < 16) ((float4*)qs)[lane] = ((const float4*)(T + m*KD_))[lane];
        __syncwarp();
        float acc[8] = {0.f,0.f,0.f,0.f,0.f,0.f,0.f,0.f};
        #pragma unroll
        for (int d4 = 0; d4 < 16; d4++) {
            float4 q4 = ((float4*)qs)[d4];
            float qq[4] = {q4.x, q4.y, q4.z, q4.w};
            #pragma unroll
            for (int qi = 0; qi < 4; qi++) {
                const float* rr2 = rbase + (d4*4 + qi)*R_;
                float4 rA = *(const float4*)rr2;
                float4 rB = *(const float4*)(rr2 + 4);
                acc[0] += qq[qi]*rA.x; acc[1] += qq[qi]*rA.y;
                acc[2] += qq[qi]*rA.z; acc[3] += qq[qi]*rA.w;
                acc[4] += qq[qi]*rB.x; acc[5] += qq[qi]*rB.y;
                acc[6] += qq[qi]*rB.z; acc[7] += qq[qi]*rB.w;
            }
        }
        float mx = -1e30f;
        #pragma unroll
        for (int j = 0; j < 8; j++) { acc[j] *= SCALE_; mx = fmaxf(mx, acc[j]); }
        #pragma unroll
        for (int off = 16; off >= 1; off >>= 1)
            mx = fmaxf(mx, __shfl_xor_sync(0xffffffffu, mx, off));
        float4 o0, o1;
        o0.x = __expf(acc[0]-mx)+EPS_; o0.y = __expf(acc[1]-mx)+EPS_;
        o0.z = __expf(acc[2]-mx)+EPS_; o0.w = __expf(acc[3]-mx)+EPS_;
        o1.x = __expf(acc[4]-mx)+EPS_; o1.y = __expf(acc[5]-mx)+EPS_;
        o1.z = __expf(acc[6]-mx)+EPS_; o1.w = __expf(acc[7]-mx)+EPS_;
        float4* dst = (float4*)(outF + m*R_);
        dst[lane*2]   = o0;
        dst[lane*2+1] = o1;
        __syncwarp();
    }
}

// ---------------- kv partial: kvp[bh,sp,r,d] = sum_{s in split} kf*v; ksump likewise ----
__global__ void kvsum_kernel(const float* __restrict__ kf, const float* __restrict__ v,
                             float* __restrict__ kvp, float* __restrict__ ksump) {
    __shared__ float kfs[32*256];
    __shared__ float vs[32*64];
    int bh = blockIdx.x, sp = blockIdx.y;
    int b = bh >> 3, h = bh & 7;
    int t = threadIdx.x, tx = t & 15, ty = t >> 4;
    float acc[16][4] = {};
    float ks = 0.f;
    int sbase = sp*256;
    for (int s0 = 0; s0 < 256; s0 += 32) {
        #pragma unroll
        for (int j = 0; j < 8; j++) {
            int idx = t + 256*j;
            int si = idx >> 6, c = idx & 63;
            size_t row = (size_t)(b*S_ + sbase + s0 + si)*H_ + h;
            ((float4*)kfs)[idx] = ((const float4*)(kf + row*R_))[c];
        }
        #pragma unroll
        for (int j = 0; j < 2; j++) {
            int idx = t + 256*j;
            int si = idx >> 4, c = idx & 15;
            size_t row = (size_t)(b*S_ + sbase + s0 + si)*H_ + h;
            ((float4*)vs)[idx] = ((const float4*)(v + row*KD_))[c];
        }
        __syncthreads();
        for (int si = 0; si < 32; si++) {
            ks += kfs[si*256 + t];
            float4 v4 = ((float4*)(vs + si*64))[tx];
            #pragma unroll
            for (int i = 0; i < 16; i++) {
                float a = kfs[si*256 + ty + 16*i];
                acc[i][0] += a*v4.x; acc[i][1] += a*v4.y;
                acc[i][2] += a*v4.z; acc[i][3] += a*v4.w;
            }
        }
        __syncthreads();
    }
    size_t base = ((size_t)bh*NSPLIT + sp)*R_;
    ksump[base + t] = ks;
    #pragma unroll
    for (int i = 0; i < 16; i++) {
        float4 o = make_float4(acc[i][0], acc[i][1], acc[i][2], acc[i][3]);
        *(float4*)(kvp + (base + ty + 16*i)*KD_ + tx*4) = o;
    }
}

// ---------------- deterministic split reduce ----------------
__global__ void reduce_kernel(const float* __restrict__ kvp, const float* __restrict__ ksump,
                              float* __restrict__ kv, float* __restrict__ ksum) {
    int idx = blockIdx.x*256 + threadIdx.x;
    const int NKV = B_*H_*R_*KD_;  // 524288
    if (idx < NKV) {
        int bh = idx >> 14;
        int rd = idx & 16383;
        float s = 0.f;
        #pragma unroll
        for (int sp = 0; sp < NSPLIT; sp++)
            s += kvp[((size_t)(bh*NSPLIT + sp) << 14) + rd];
        kv[idx] = s;
    } else {
        int j = idx - NKV;
        if (j < B_*H_*R_) {
            int bh = j >> 8, r = j & 255;
            float s = 0.f;
            #pragma unroll
            for (int sp = 0; sp < NSPLIT; sp++)
                s += ksump[(bh*NSPLIT + sp)*R_ + r];
            ksum[j] = s;
        }
    }
}

// ---------------- attn: num = qf@kv, den = qf.ksum + EPS, attn = num/den ----------------
__global__ void attn_kernel(const float* __restrict__ qf, const float* __restrict__ kv,
                            const float* __restrict__ ksum, float* __restrict__ attn) {
    __shared__ float qfs[64*32];
    __shared__ float kvs[32*64];
    __shared__ float kss[256];
    int bh = blockIdx.x, b = bh >> 3, h = bh & 7;
    int s0 = blockIdx.y * 64;
    int t = threadIdx.x, tx = t & 15, ty = t >> 4;
    kss[t] = ksum[bh*R_ + t];
    float acc[4][4] = {};
    float den[4] = {};
    for (int rb = 0; rb < R_; rb += 32) {
        #pragma unroll
        for (int j = 0; j < 2; j++) {
            int idx = t + 256*j;
            int row = idx >> 3, c = idx & 7;
            size_t g = ((size_t)(b*S_ + s0 + row)*H_ + h)*R_ + rb;
            ((float4*)qfs)[idx] = ((const float4*)(qf + g))[c];
        }
        #pragma unroll
        for (int j = 0; j < 2; j++) {
            int idx = t + 256*j;
            int k = idx >> 4, c = idx & 15;
            ((float4*)kvs)[idx] = ((const float4*)(kv + ((size_t)bh*R_ + rb + k)*KD_))[c];
        }
        __syncthreads();
        #pragma unroll
        for (int k = 0; k < 32; k++) {
            float4 b4 = ((float4*)(kvs + k*64))[tx];
            float ksv = kss[rb + k];
            #pragma unroll
            for (int i = 0; i < 4; i++) {
                float a = qfs[(ty*4+i)*32 + k];
                den[i] += a*ksv;
                acc[i][0] += a*b4.x; acc[i][1] += a*b4.y;
                acc[i][2] += a*b4.z; acc[i][3] += a*b4.w;
            }
        }
        __syncthreads();
    }
    #pragma unroll
    for (int i = 0; i < 4; i++) {
        int s = s0 + ty*4 + i;
        float inv = 1.0f / (den[i] + EPS_);
        float4 o = make_float4(acc[i][0]*inv, acc[i][1]*inv, acc[i][2]*inv, acc[i][3]*inv);
        *(float4*)(attn + (size_t)(b*S_ + s)*D_ + h*KD_ + tx*4) = o;
    }
}

// ---------------- launch ----------------
extern "C" void kernel_launch(void* const* d_in, const int* in_sizes, int n_in,
                              void* d_out, int out_size) {
    const float* x  = (const float*)d_in[0];
    const float* Wq = (const float*)d_in[1];
    const float* Wk = (const float*)d_in[2];
    const float* Wv = (const float*)d_in[3];
    const float* rf = (const float*)d_in[4];
    const float* Wo = (const float*)d_in[5];
    const float* bo = (const float*)d_in[6];
    float* out = (float*)d_out;

    float *pq, *pk, *pv, *pqf, *pkf, *pkvp, *pksp, *pkv, *pks, *pattn;
    cudaGetSymbolAddress((void**)&pq,   g_q);
    cudaGetSymbolAddress((void**)&pk,   g_k);
    cudaGetSymbolAddress((void**)&pv,   g_v);
    cudaGetSymbolAddress((void**)&pqf,  g_qf);
    cudaGetSymbolAddress((void**)&pkf,  g_kf);
    cudaGetSymbolAddress((void**)&pkvp, g_kvp);
    cudaGetSymbolAddress((void**)&pksp, g_ksump);
    cudaGetSymbolAddress((void**)&pkv,  g_kv);
    cudaGetSymbolAddress((void**)&pks,  g_ksum);
    cudaGetSymbolAddress((void**)&pattn,g_attn);

    const int fsm = 64*256*4 + 8*64*4;  // rfT + per-warp row buffers = 67584 B
    cudaFuncSetAttribute(feat_kernel, cudaFuncAttributeMaxDynamicSharedMemorySize, fsm);

    dim3 gg(D_/64, M_/64);   // (8, 256)

    gemm64<<<gg, 256>>>(x, Wq, pq, nullptr, M_, D_, D_);
    gemm64<<<gg, 256>>>(x, Wk, pk, nullptr, M_, D_, D_);
    gemm64<<<gg, 256>>>(x, Wv, pv, nullptr, M_, D_, D_);

    feat_kernel<<<ROWS_/128, 256, fsm>>>(pq, rf, pqf);
    feat_kernel<<<ROWS_/128, 256, fsm>>>(pk, rf, pkf);

    kvsum_kernel<<<dim3(B_*H_, NSPLIT), 256>>>(pkf, pv, pkvp, pksp);
    reduce_kernel<<<(B_*H_*R_*KD_ + B_*H_*R_ + 255)/256, 256>>>(pkvp, pksp, pkv, pks);

    attn_kernel<<<dim3(B_*H_, S_/64), 256>>>(pqf, pkv, pks, pattn);

    gemm64<<<gg, 256>>>(pattn, Wo, out, bo, M_, D_, D_);
}

// round 2
// speedup vs baseline: 1.7403x; 1.7403x over previous
#include <cuda_runtime.h>
#include <math.h>

#define B_   4
#define S_   4096
#define D_   512
#define H_   8
#define KD_  64
#define R_   256
#define M_   (B_*S_)       // 16384 rows of x
#define ROWS_ (M_*H_)      // 131072 (b,s,h) rows
#define EPS_ 1e-3f
#define SCALE_ 0.125f      // 1/sqrt(64)
#define NSPLIT 16

// ---------------- scratch (static device globals; no runtime allocation) ----------------
__device__ float g_q[M_*D_];
__device__ float g_k[M_*D_];
__device__ float g_v[M_*D_];
__device__ float g_qf[(size_t)ROWS_*R_];      // 128 MB
__device__ float g_kf[(size_t)ROWS_*R_];      // 128 MB
__device__ float g_kvp[B_*H_*NSPLIT*R_*KD_];  // split partials
__device__ float g_ksump[B_*H_*NSPLIT*R_];
__device__ float g_kv[B_*H_*R_*KD_];
__device__ float g_ksum[B_*H_*R_];
__device__ float g_attn[M_*D_];

// ---------------- generic fp32 GEMM: C[M,N] = A[M,K] @ B[K,N] (+bias) ----------------
// BM=BN=64, BK=16, 256 threads, 4x4 microtile.
__global__ void gemm64(const float* __restrict__ A, const float* __restrict__ Bm,
                       float* __restrict__ C, const float* __restrict__ bias,
                       int M, int N, int K) {
    __shared__ float As[16][64];
    __shared__ float Bs[16][64];
    int bx = blockIdx.x, by = blockIdx.y;
    int t = threadIdx.x;
    int tx = t & 15, ty = t >> 4;
    float acc[4][4] = {};
    int arow = t >> 2, ac = t & 3;     // A tile: 64 rows x 4 float4 cols
    int brow = t >> 4, bc = t & 15;    // B tile: 16 rows x 16 float4 cols
    const float* Ap = A + (size_t)(by*64 + arow)*K + ac*4;
    const float* Bp = Bm + (size_t)brow*N + bx*64 + bc*4;

    for (int kb = 0; kb < K; kb += 16) {
        float4 a4 = *(const float4*)(Ap + kb);
        float4 b4 = *(const float4*)(Bp + (size_t)kb*N);
        As[ac*4+0][arow] = a4.x;
        As[ac*4+1][arow] = a4.y;
        As[ac*4+2][arow] = a4.z;
        As[ac*4+3][arow] = a4.w;
        *(float4*)&Bs[brow][bc*4] = b4;
        __syncthreads();
        #pragma unroll
        for (int k = 0; k < 16; k++) {
            float4 af = *(float4*)&As[k][ty*4];
            float4 bf = *(float4*)&Bs[k][tx*4];
            acc[0][0] += af.x*bf.x; acc[0][1] += af.x*bf.y; acc[0][2] += af.x*bf.z; acc[0][3] += af.x*bf.w;
            acc[1][0] += af.y*bf.x; acc[1][1] += af.y*bf.y; acc[1][2] += af.y*bf.z; acc[1][3] += af.y*bf.w;
            acc[2][0] += af.z*bf.x; acc[2][1] += af.z*bf.y; acc[2][2] += af.z*bf.z; acc[2][3] += af.z*bf.w;
            acc[3][0] += af.w*bf.x; acc[3][1] += af.w*bf.y; acc[3][2] += af.w*bf.z; acc[3][3] += af.w*bf.w;
        }
        __syncthreads();
    }
    int col = bx*64 + tx*4;
    float4 bb = bias ? *(const float4*)(bias + col) : make_float4(0.f,0.f,0.f,0.f);
    #pragma unroll
    for (int i = 0; i < 4; i++) {
        int row = by*64 + ty*4 + i;
        float4 o = make_float4(acc[i][0]+bb.x, acc[i][1]+bb.y, acc[i][2]+bb.z, acc[i][3]+bb.w);
        *(float4*)(C + (size_t)row*N + col) = o;
    }
}

// ---------------- feature kernel (GEMM-style, 8x8 microtile) ----------------
// outF[m, r] = exp(SCALE * (T[m,:] . rf[r,:]) - rowmax) + EPS
// BM=64, BN=256 (all of R), BK=16 staged. 256 threads.
// Warp = fixed row-group of 8 rows; 32 lanes tile the 256 cols in 8-wide chunks
// -> A reads are warp-broadcast, B reads conflict-free LDS.128, rowmax is a
//    pure intra-warp shfl reduction.
__global__ void __launch_bounds__(256) feat_kernel(
        const float* __restrict__ T, const float* __restrict__ rf,
        float* __restrict__ outF) {
    __shared__ float As[16][64];
    __shared__ float Bs[16][256];
    int t = threadIdx.x;
    int tx = t & 31;          // col group: cols tx*8 .. tx*8+7
    int ty = t >> 5;          // row group: rows ty*8 .. ty*8+7 (warp id)
    size_t m0 = (size_t)blockIdx.x * 64;
    float acc[8][8] = {};

    int arow = t >> 2, ac = t & 3;      // A tile loader mapping

    for (int kb = 0; kb < KD_; kb += 16) {
        // stage A: 64 rows x 16 k (transposed into As[k][row])
        float4 a4 = *(const float4*)(T + (m0 + arow)*KD_ + kb + ac*4);
        As[ac*4+0][arow] = a4.x;
        As[ac*4+1][arow] = a4.y;
        As[ac*4+2][arow] = a4.z;
        As[ac*4+3][arow] = a4.w;
        // stage B: Bs[k][r] = rf[r*64 + kb + k]; 4 float4 gathers per thread
        #pragma unroll
        for (int j = 0; j < 4; j++) {
            int idx = t + 256*j;          // 0..1023
            int r = idx >> 2, dq = idx & 3;
            float4 b4 = *(const float4*)(rf + r*KD_ + kb + dq*4);
            Bs[dq*4+0][r] = b4.x;
            Bs[dq*4+1][r] = b4.y;
            Bs[dq*4+2][r] = b4.z;
            Bs[dq*4+3][r] = b4.w;
        }
        __syncthreads();
        #pragma unroll
        for (int k = 0; k < 16; k++) {
            float4 a0 = *(float4*)&As[k][ty*8];
            float4 a1 = *(float4*)&As[k][ty*8+4];
            float4 b0 = *(float4*)&Bs[k][tx*8];
            float4 b1 = *(float4*)&Bs[k][tx*8+4];
            float av[8] = {a0.x,a0.y,a0.z,a0.w,a1.x,a1.y,a1.z,a1.w};
            float bv[8] = {b0.x,b0.y,b0.z,b0.w,b1.x,b1.y,b1.z,b1.w};
            #pragma unroll
            for (int i = 0; i < 8; i++)
                #pragma unroll
                for (int j = 0; j < 8; j++)
                    acc[i][j] += av[i]*bv[j];
        }
        __syncthreads();
    }

    // epilogue: scale, per-row max (intra-warp), exp + EPS, store
    #pragma unroll
    for (int i = 0; i < 8; i++) {
        float mx = -1e30f;
        #pragma unroll
        for (int j = 0; j < 8; j++) {
            acc[i][j] *= SCALE_;
            mx = fmaxf(mx, acc[i][j]);
        }
        #pragma unroll
        for (int off = 16; off >= 1; off >>= 1)
            mx = fmaxf(mx, __shfl_xor_sync(0xffffffffu, mx, off));
        float4 o0, o1;
        o0.x = __expf(acc[i][0]-mx)+EPS_; o0.y = __expf(acc[i][1]-mx)+EPS_;
        o0.z = __expf(acc[i][2]-mx)+EPS_; o0.w = __expf(acc[i][3]-mx)+EPS_;
        o1.x = __expf(acc[i][4]-mx)+EPS_; o1.y = __expf(acc[i][5]-mx)+EPS_;
        o1.z = __expf(acc[i][6]-mx)+EPS_; o1.w = __expf(acc[i][7]-mx)+EPS_;
        size_t m = m0 + ty*8 + i;
        float4* dst = (float4*)(outF + m*R_ + tx*8);
        dst[0] = o0;
        dst[1] = o1;
    }
}

// ---------------- kv partial: kvp[bh,sp,r,d] = sum_{s in split} kf*v; ksump likewise ----
__global__ void kvsum_kernel(const float* __restrict__ kf, const float* __restrict__ v,
                             float* __restrict__ kvp, float* __restrict__ ksump) {
    __shared__ float kfs[32*256];
    __shared__ float vs[32*64];
    int bh = blockIdx.x, sp = blockIdx.y;
    int b = bh >> 3, h = bh & 7;
    int t = threadIdx.x, tx = t & 15, ty = t >> 4;
    float acc[16][4] = {};
    float ks = 0.f;
    int sbase = sp*256;
    for (int s0 = 0; s0 < 256; s0 += 32) {
        #pragma unroll
        for (int j = 0; j < 8; j++) {
            int idx = t + 256*j;
            int si = idx >> 6, c = idx & 63;
            size_t row = (size_t)(b*S_ + sbase + s0 + si)*H_ + h;
            ((float4*)kfs)[idx] = ((const float4*)(kf + row*R_))[c];
        }
        #pragma unroll
        for (int j = 0; j < 2; j++) {
            int idx = t + 256*j;
            int si = idx >> 4, c = idx & 15;
            size_t row = (size_t)(b*S_ + sbase + s0 + si)*H_ + h;
            ((float4*)vs)[idx] = ((const float4*)(v + row*KD_))[c];
        }
        __syncthreads();
        for (int si = 0; si < 32; si++) {
            ks += kfs[si*256 + t];
            float4 v4 = ((float4*)(vs + si*64))[tx];
            #pragma unroll
            for (int i = 0; i < 16; i++) {
                float a = kfs[si*256 + ty + 16*i];
                acc[i][0] += a*v4.x; acc[i][1] += a*v4.y;
                acc[i][2] += a*v4.z; acc[i][3] += a*v4.w;
            }
        }
        __syncthreads();
    }
    size_t base = ((size_t)bh*NSPLIT + sp)*R_;
    ksump[base + t] = ks;
    #pragma unroll
    for (int i = 0; i < 16; i++) {
        float4 o = make_float4(acc[i][0], acc[i][1], acc[i][2], acc[i][3]);
        *(float4*)(kvp + (base + ty + 16*i)*KD_ + tx*4) = o;
    }
}

// ---------------- deterministic split reduce ----------------
__global__ void reduce_kernel(const float* __restrict__ kvp, const float* __restrict__ ksump,
                              float* __restrict__ kv, float* __restrict__ ksum) {
    int idx = blockIdx.x*256 + threadIdx.x;
    const int NKV = B_*H_*R_*KD_;  // 524288
    if (idx < NKV) {
        int bh = idx >> 14;
        int rd = idx & 16383;
        float s = 0.f;
        #pragma unroll
        for (int sp = 0; sp < NSPLIT; sp++)
            s += kvp[((size_t)(bh*NSPLIT + sp) << 14) + rd];
        kv[idx] = s;
    } else {
        int j = idx - NKV;
        if (j < B_*H_*R_) {
            int bh = j >> 8, r = j & 255;
            float s = 0.f;
            #pragma unroll
            for (int sp = 0; sp < NSPLIT; sp++)
                s += ksump[(bh*NSPLIT + sp)*R_ + r];
            ksum[j] = s;
        }
    }
}

// ---------------- attn: num = qf@kv, den = qf.ksum + EPS, attn = num/den ----------------
__global__ void attn_kernel(const float* __restrict__ qf, const float* __restrict__ kv,
                            const float* __restrict__ ksum, float* __restrict__ attn) {
    __shared__ float qfs[64*32];
    __shared__ float kvs[32*64];
    __shared__ float kss[256];
    int bh = blockIdx.x, b = bh >> 3, h = bh & 7;
    int s0 = blockIdx.y * 64;
    int t = threadIdx.x, tx = t & 15, ty = t >> 4;
    kss[t] = ksum[bh*R_ + t];
    float acc[4][4] = {};
    float den[4] = {};
    for (int rb = 0; rb < R_; rb += 32) {
        #pragma unroll
        for (int j = 0; j < 2; j++) {
            int idx = t + 256*j;
            int row = idx >> 3, c = idx & 7;
            size_t g = ((size_t)(b*S_ + s0 + row)*H_ + h)*R_ + rb;
            ((float4*)qfs)[idx] = ((const float4*)(qf + g))[c];
        }
        #pragma unroll
        for (int j = 0; j < 2; j++) {
            int idx = t + 256*j;
            int k = idx >> 4, c = idx & 15;
            ((float4*)kvs)[idx] = ((const float4*)(kv + ((size_t)bh*R_ + rb + k)*KD_))[c];
        }
        __syncthreads();
        #pragma unroll
        for (int k = 0; k < 32; k++) {
            float4 b4 = ((float4*)(kvs + k*64))[tx];
            float ksv = kss[rb + k];
            #pragma unroll
            for (int i = 0; i < 4; i++) {
                float a = qfs[(ty*4+i)*32 + k];
                den[i] += a*ksv;
                acc[i][0] += a*b4.x; acc[i][1] += a*b4.y;
                acc[i][2] += a*b4.z; acc[i][3] += a*b4.w;
            }
        }
        __syncthreads();
    }
    #pragma unroll
    for (int i = 0; i < 4; i++) {
        int s = s0 + ty*4 + i;
        float inv = 1.0f / (den[i] + EPS_);
        float4 o = make_float4(acc[i][0]*inv, acc[i][1]*inv, acc[i][2]*inv, acc[i][3]*inv);
        *(float4*)(attn + (size_t)(b*S_ + s)*D_ + h*KD_ + tx*4) = o;
    }
}

// ---------------- launch ----------------
extern "C" void kernel_launch(void* const* d_in, const int* in_sizes, int n_in,
                              void* d_out, int out_size) {
    const float* x  = (const float*)d_in[0];
    const float* Wq = (const float*)d_in[1];
    const float* Wk = (const float*)d_in[2];
    const float* Wv = (const float*)d_in[3];
    const float* rf = (const float*)d_in[4];
    const float* Wo = (const float*)d_in[5];
    const float* bo = (const float*)d_in[6];
    float* out = (float*)d_out;

    float *pq, *pk, *pv, *pqf, *pkf, *pkvp, *pksp, *pkv, *pks, *pattn;
    cudaGetSymbolAddress((void**)&pq,   g_q);
    cudaGetSymbolAddress((void**)&pk,   g_k);
    cudaGetSymbolAddress((void**)&pv,   g_v);
    cudaGetSymbolAddress((void**)&pqf,  g_qf);
    cudaGetSymbolAddress((void**)&pkf,  g_kf);
    cudaGetSymbolAddress((void**)&pkvp, g_kvp);
    cudaGetSymbolAddress((void**)&pksp, g_ksump);
    cudaGetSymbolAddress((void**)&pkv,  g_kv);
    cudaGetSymbolAddress((void**)&pks,  g_ksum);
    cudaGetSymbolAddress((void**)&pattn,g_attn);

    dim3 gg(D_/64, M_/64);   // (8, 256)

    gemm64<<<gg, 256>>>(x, Wq, pq, nullptr, M_, D_, D_);
    gemm64<<<gg, 256>>>(x, Wk, pk, nullptr, M_, D_, D_);
    gemm64<<<gg, 256>>>(x, Wv, pv, nullptr, M_, D_, D_);

    feat_kernel<<<ROWS_/64, 256>>>(pq, rf, pqf);
    feat_kernel<<<ROWS_/64, 256>>>(pk, rf, pkf);

    kvsum_kernel<<<dim3(B_*H_, NSPLIT), 256>>>(pkf, pv, pkvp, pksp);
    reduce_kernel<<<(B_*H_*R_*KD_ + B_*H_*R_ + 255)/256, 256>>>(pkvp, pksp, pkv, pks);

    attn_kernel<<<dim3(B_*H_, S_/64), 256>>>(pqf, pkv, pks, pattn);

    gemm64<<<gg, 256>>>(pattn, Wo, out, bo, M_, D_, D_);
}

// round 3
// speedup vs baseline: 1.8925x; 1.0875x over previous
#include <cuda_runtime.h>
#include <math.h>

#define B_   4
#define S_   4096
#define D_   512
#define H_   8
#define KD_  64
#define R_   256
#define M_   (B_*S_)       // 16384 rows of x
#define ROWS_ (M_*H_)      // 131072 (b,s,h) rows
#define EPS_ 1e-3f
#define SCALE_ 0.125f      // 1/sqrt(64)
#define NSPLIT 16

typedef unsigned long long ull;

// ---- packed f32x2 helpers (FFMA2: 2 fp32 FMAs per instruction, identical rounding) ----
__device__ __forceinline__ ull pk2(float a, float b) {
    ull r; asm("mov.b64 %0, {%1,%2};" : "=l"(r) : "f"(a), "f"(b)); return r;
}
__device__ __forceinline__ void fma2(ull& d, ull a, ull b) {
    asm("fma.rn.f32x2 %0, %1, %2, %0;" : "+l"(d) : "l"(a), "l"(b));
}
__device__ __forceinline__ float2 up2(ull v) {
    float2 f; asm("mov.b64 {%0,%1}, %2;" : "=f"(f.x), "=f"(f.y) : "l"(v)); return f;
}

// ---------------- scratch (static device globals; no runtime allocation) ----------------
__device__ float g_q[M_*D_];
__device__ float g_k[M_*D_];
__device__ float g_v[M_*D_];
__device__ float g_qf[(size_t)ROWS_*R_];      // 128 MB
__device__ float g_kf[(size_t)ROWS_*R_];      // 128 MB
__device__ float g_kvp[B_*H_*NSPLIT*R_*KD_];  // split partials
__device__ float g_ksump[B_*H_*NSPLIT*R_];
__device__ float g_kv[B_*H_*R_*KD_];
__device__ float g_ksum[B_*H_*R_];
__device__ float g_attn[M_*D_];

// ---------------- dense GEMM, packed f32x2: C[M,512] = A[M,512] @ B[512,512] (+bias) ----
// BM=64, BN=256, BK=16, 256 threads, 8x8 microtile (32 FFMA2 per k-step).
__global__ void __launch_bounds__(256) gemm_big(
        const float* __restrict__ A, const float* __restrict__ Bm,
        float* __restrict__ C, const float* __restrict__ bias) {
    __shared__ float As[16][64];
    __shared__ float Bs[16][256];
    int t = threadIdx.x;
    int tx = t & 31;          // col group: cols tx*8 .. +7
    int ty = t >> 5;          // row group: rows ty*8 .. +7 (warp id)
    size_t m0 = (size_t)blockIdx.y * 64;
    int n0 = blockIdx.x * 256;
    ull acc[8][4] = {};

    int arow = t >> 2, ac = t & 3;

    for (int kb = 0; kb < D_; kb += 16) {
        float4 a4 = *(const float4*)(A + (m0 + arow)*D_ + kb + ac*4);
        As[ac*4+0][arow] = a4.x;
        As[ac*4+1][arow] = a4.y;
        As[ac*4+2][arow] = a4.z;
        As[ac*4+3][arow] = a4.w;
        #pragma unroll
        for (int j = 0; j < 4; j++) {
            int idx = t + 256*j;           // 0..1023
            int k = idx >> 6, c4 = idx & 63;
            float4 b4 = *(const float4*)(Bm + (size_t)(kb + k)*D_ + n0 + c4*4);
            *(float4*)&Bs[k][c4*4] = b4;
        }
        __syncthreads();
        #pragma unroll
        for (int k = 0; k < 16; k++) {
            float4 a0 = *(float4*)&As[k][ty*8];
            float4 a1 = *(float4*)&As[k][ty*8+4];
            float4 b0 = *(float4*)&Bs[k][tx*8];
            float4 b1 = *(float4*)&Bs[k][tx*8+4];
            ull bp[4] = {pk2(b0.x,b0.y), pk2(b0.z,b0.w), pk2(b1.x,b1.y), pk2(b1.z,b1.w)};
            float av[8] = {a0.x,a0.y,a0.z,a0.w,a1.x,a1.y,a1.z,a1.w};
            #pragma unroll
            for (int i = 0; i < 8; i++) {
                ull aa = pk2(av[i], av[i]);
                #pragma unroll
                for (int j = 0; j < 4; j++)
                    fma2(acc[i][j], aa, bp[j]);
            }
        }
        __syncthreads();
    }

    int col = n0 + tx*8;
    float4 bb0 = make_float4(0.f,0.f,0.f,0.f), bb1 = bb0;
    if (bias) {
        bb0 = *(const float4*)(bias + col);
        bb1 = *(const float4*)(bias + col + 4);
    }
    #pragma unroll
    for (int i = 0; i < 8; i++) {
        float2 p0 = up2(acc[i][0]), p1 = up2(acc[i][1]);
        float2 p2 = up2(acc[i][2]), p3 = up2(acc[i][3]);
        size_t m = m0 + ty*8 + i;
        float4 o0 = make_float4(p0.x+bb0.x, p0.y+bb0.y, p1.x+bb0.z, p1.y+bb0.w);
        float4 o1 = make_float4(p2.x+bb1.x, p2.y+bb1.y, p3.x+bb1.z, p3.y+bb1.w);
        *(float4*)(C + m*D_ + col)     = o0;
        *(float4*)(C + m*D_ + col + 4) = o1;
    }
}

// ---------------- feature kernel (packed f32x2, 8x8 microtile) ----------------
// outF[m, r] = exp(SCALE * (T[m,:] . rf[r,:]) - rowmax) + EPS
__global__ void __launch_bounds__(256) feat_kernel(
        const float* __restrict__ T, const float* __restrict__ rf,
        float* __restrict__ outF) {
    __shared__ float As[16][64];
    __shared__ float Bs[16][256];
    int t = threadIdx.x;
    int tx = t & 31;
    int ty = t >> 5;
    size_t m0 = (size_t)blockIdx.x * 64;
    ull acc[8][4] = {};

    int arow = t >> 2, ac = t & 3;

    for (int kb = 0; kb < KD_; kb += 16) {
        float4 a4 = *(const float4*)(T + (m0 + arow)*KD_ + kb + ac*4);
        As[ac*4+0][arow] = a4.x;
        As[ac*4+1][arow] = a4.y;
        As[ac*4+2][arow] = a4.z;
        As[ac*4+3][arow] = a4.w;
        #pragma unroll
        for (int j = 0; j < 4; j++) {
            int idx = t + 256*j;
            int r = idx >> 2, dq = idx & 3;
            float4 b4 = *(const float4*)(rf + r*KD_ + kb + dq*4);
            Bs[dq*4+0][r] = b4.x;
            Bs[dq*4+1][r] = b4.y;
            Bs[dq*4+2][r] = b4.z;
            Bs[dq*4+3][r] = b4.w;
        }
        __syncthreads();
        #pragma unroll
        for (int k = 0; k < 16; k++) {
            float4 a0 = *(float4*)&As[k][ty*8];
            float4 a1 = *(float4*)&As[k][ty*8+4];
            float4 b0 = *(float4*)&Bs[k][tx*8];
            float4 b1 = *(float4*)&Bs[k][tx*8+4];
            ull bp[4] = {pk2(b0.x,b0.y), pk2(b0.z,b0.w), pk2(b1.x,b1.y), pk2(b1.z,b1.w)};
            float av[8] = {a0.x,a0.y,a0.z,a0.w,a1.x,a1.y,a1.z,a1.w};
            #pragma unroll
            for (int i = 0; i < 8; i++) {
                ull aa = pk2(av[i], av[i]);
                #pragma unroll
                for (int j = 0; j < 4; j++)
                    fma2(acc[i][j], aa, bp[j]);
            }
        }
        __syncthreads();
    }

    #pragma unroll
    for (int i = 0; i < 8; i++) {
        float2 p0 = up2(acc[i][0]), p1 = up2(acc[i][1]);
        float2 p2 = up2(acc[i][2]), p3 = up2(acc[i][3]);
        float v[8] = {p0.x,p0.y,p1.x,p1.y,p2.x,p2.y,p3.x,p3.y};
        float mx = -1e30f;
        #pragma unroll
        for (int j = 0; j < 8; j++) {
            v[j] *= SCALE_;
            mx = fmaxf(mx, v[j]);
        }
        #pragma unroll
        for (int off = 16; off >= 1; off >>= 1)
            mx = fmaxf(mx, __shfl_xor_sync(0xffffffffu, mx, off));
        float4 o0, o1;
        o0.x = __expf(v[0]-mx)+EPS_; o0.y = __expf(v[1]-mx)+EPS_;
        o0.z = __expf(v[2]-mx)+EPS_; o0.w = __expf(v[3]-mx)+EPS_;
        o1.x = __expf(v[4]-mx)+EPS_; o1.y = __expf(v[5]-mx)+EPS_;
        o1.z = __expf(v[6]-mx)+EPS_; o1.w = __expf(v[7]-mx)+EPS_;
        size_t m = m0 + ty*8 + i;
        float4* dst = (float4*)(outF + m*R_ + tx*8);
        dst[0] = o0;
        dst[1] = o1;
    }
}

// ---------------- kv partial: kvp[bh,sp,r,d] = sum_{s in split} kf*v; ksump likewise ----
// Thread row mapping is contiguous (ty*16 + i) so kf operands pair into LDS.64 broadcasts.
__global__ void kvsum_kernel(const float* __restrict__ kf, const float* __restrict__ v,
                             float* __restrict__ kvp, float* __restrict__ ksump) {
    __shared__ float kfs[32*256];
    __shared__ float vs[32*64];
    int bh = blockIdx.x, sp = blockIdx.y;
    int b = bh >> 3, h = bh & 7;
    int t = threadIdx.x, tx = t & 15, ty = t >> 4;
    ull acc[8][4] = {};          // pairs of rows (2*i2, 2*i2+1) x 4 v-cols
    float ks = 0.f;
    int sbase = sp*256;
    for (int s0 = 0; s0 < 256; s0 += 32) {
        #pragma unroll
        for (int j = 0; j < 8; j++) {
            int idx = t + 256*j;
            int si = idx >> 6, c = idx & 63;
            size_t row = (size_t)(b*S_ + sbase + s0 + si)*H_ + h;
            ((float4*)kfs)[idx] = ((const float4*)(kf + row*R_))[c];
        }
        #pragma unroll
        for (int j = 0; j < 2; j++) {
            int idx = t + 256*j;
            int si = idx >> 4, c = idx & 15;
            size_t row = (size_t)(b*S_ + sbase + s0 + si)*H_ + h;
            ((float4*)vs)[idx] = ((const float4*)(v + row*KD_))[c];
        }
        __syncthreads();
        for (int si = 0; si < 32; si++) {
            ks += kfs[si*256 + t];
            float4 v4 = ((float4*)(vs + si*64))[tx];
            ull vd[4] = {pk2(v4.x,v4.x), pk2(v4.y,v4.y), pk2(v4.z,v4.z), pk2(v4.w,v4.w)};
            const float2* arow = (const float2*)(kfs + si*256 + ty*16);
            #pragma unroll
            for (int i2 = 0; i2 < 8; i2++) {
                float2 ap = arow[i2];
                ull aa = pk2(ap.x, ap.y);
                #pragma unroll
                for (int j = 0; j < 4; j++)
                    fma2(acc[i2][j], aa, vd[j]);
            }
        }
        __syncthreads();
    }
    size_t base = ((size_t)bh*NSPLIT + sp)*R_;
    ksump[base + t] = ks;
    #pragma unroll
    for (int i2 = 0; i2 < 8; i2++) {
        float2 c0 = up2(acc[i2][0]), c1 = up2(acc[i2][1]);
        float2 c2 = up2(acc[i2][2]), c3 = up2(acc[i2][3]);
        int r0 = ty*16 + 2*i2;
        *(float4*)(kvp + (base + r0)*KD_ + tx*4)     = make_float4(c0.x, c1.x, c2.x, c3.x);
        *(float4*)(kvp + (base + r0 + 1)*KD_ + tx*4) = make_float4(c0.y, c1.y, c2.y, c3.y);
    }
}

// ---------------- deterministic split reduce ----------------
__global__ void reduce_kernel(const float* __restrict__ kvp, const float* __restrict__ ksump,
                              float* __restrict__ kv, float* __restrict__ ksum) {
    int idx = blockIdx.x*256 + threadIdx.x;
    const int NKV = B_*H_*R_*KD_;  // 524288
    if (idx < NKV) {
        int bh = idx >> 14;
        int rd = idx & 16383;
        float s = 0.f;
        #pragma unroll
        for (int sp = 0; sp < NSPLIT; sp++)
            s += kvp[((size_t)(bh*NSPLIT + sp) << 14) + rd];
        kv[idx] = s;
    } else {
        int j = idx - NKV;
        if (j < B_*H_*R_) {
            int bh = j >> 8, r = j & 255;
            float s = 0.f;
            #pragma unroll
            for (int sp = 0; sp < NSPLIT; sp++)
                s += ksump[(bh*NSPLIT + sp)*R_ + r];
            ksum[j] = s;
        }
    }
}

// ---------------- attn: num = qf@kv, den = qf.ksum + EPS, attn = num/den ----------------
__global__ void attn_kernel(const float* __restrict__ qf, const float* __restrict__ kv,
                            const float* __restrict__ ksum, float* __restrict__ attn) {
    __shared__ float qfs[64*32];
    __shared__ float kvs[32*64];
    __shared__ float kss[256];
    int bh = blockIdx.x, b = bh >> 3, h = bh & 7;
    int s0 = blockIdx.y * 64;
    int t = threadIdx.x, tx = t & 15, ty = t >> 4;
    kss[t] = ksum[bh*R_ + t];
    ull acc[4][2] = {};    // 4 rows x (col pairs)
    float den[4] = {};
    for (int rb = 0; rb < R_; rb += 32) {
        #pragma unroll
        for (int j = 0; j < 2; j++) {
            int idx = t + 256*j;
            int row = idx >> 3, c = idx & 7;
            size_t g = ((size_t)(b*S_ + s0 + row)*H_ + h)*R_ + rb;
            ((float4*)qfs)[idx] = ((const float4*)(qf + g))[c];
        }
        #pragma unroll
        for (int j = 0; j < 2; j++) {
            int idx = t + 256*j;
            int k = idx >> 4, c = idx & 15;
            ((float4*)kvs)[idx] = ((const float4*)(kv + ((size_t)bh*R_ + rb + k)*KD_))[c];
        }
        __syncthreads();
        #pragma unroll
        for (int k = 0; k < 32; k++) {
            float4 b4 = ((float4*)(kvs + k*64))[tx];
            ull bp0 = pk2(b4.x, b4.y), bp1 = pk2(b4.z, b4.w);
            float ksv = kss[rb + k];
            #pragma unroll
            for (int i = 0; i < 4; i++) {
                float a = qfs[(ty*4+i)*32 + k];
                den[i] += a*ksv;
                ull aa = pk2(a, a);
                fma2(acc[i][0], aa, bp0);
                fma2(acc[i][1], aa, bp1);
            }
        }
        __syncthreads();
    }
    #pragma unroll
    for (int i = 0; i < 4; i++) {
        int s = s0 + ty*4 + i;
        float inv = 1.0f / (den[i] + EPS_);
        float2 c0 = up2(acc[i][0]), c1 = up2(acc[i][1]);
        float4 o = make_float4(c0.x*inv, c0.y*inv, c1.x*inv, c1.y*inv);
        *(float4*)(attn + (size_t)(b*S_ + s)*D_ + h*KD_ + tx*4) = o;
    }
}

// ---------------- launch ----------------
extern "C" void kernel_launch(void* const* d_in, const int* in_sizes, int n_in,
                              void* d_out, int out_size) {
    const float* x  = (const float*)d_in[0];
    const float* Wq = (const float*)d_in[1];
    const float* Wk = (const float*)d_in[2];
    const float* Wv = (const float*)d_in[3];
    const float* rf = (const float*)d_in[4];
    const float* Wo = (const float*)d_in[5];
    const float* bo = (const float*)d_in[6];
    float* out = (float*)d_out;

    float *pq, *pk, *pv, *pqf, *pkf, *pkvp, *pksp, *pkv, *pks, *pattn;
    cudaGetSymbolAddress((void**)&pq,   g_q);
    cudaGetSymbolAddress((void**)&pk,   g_k);
    cudaGetSymbolAddress((void**)&pv,   g_v);
    cudaGetSymbolAddress((void**)&pqf,  g_qf);
    cudaGetSymbolAddress((void**)&pkf,  g_kf);
    cudaGetSymbolAddress((void**)&pkvp, g_kvp);
    cudaGetSymbolAddress((void**)&pksp, g_ksump);
    cudaGetSymbolAddress((void**)&pkv,  g_kv);
    cudaGetSymbolAddress((void**)&pks,  g_ksum);
    cudaGetSymbolAddress((void**)&pattn,g_attn);

    dim3 gg(D_/256, M_/64);   // (2, 256)

    gemm_big<<<gg, 256>>>(x, Wq, pq, nullptr);
    gemm_big<<<gg, 256>>>(x, Wk, pk, nullptr);
    gemm_big<<<gg, 256>>>(x, Wv, pv, nullptr);

    feat_kernel<<<ROWS_/64, 256>>>(pq, rf, pqf);
    feat_kernel<<<ROWS_/64, 256>>>(pk, rf, pkf);

    kvsum_kernel<<<dim3(B_*H_, NSPLIT), 256>>>(pkf, pv, pkvp, pksp);
    reduce_kernel<<<(B_*H_*R_*KD_ + B_*H_*R_ + 255)/256, 256>>>(pkvp, pksp, pkv, pks);

    attn_kernel<<<dim3(B_*H_, S_/64), 256>>>(pqf, pkv, pks, pattn);

    gemm_big<<<gg, 256>>>(pattn, Wo, out, bo);
}

// round 6
// speedup vs baseline: 2.9197x; 1.5428x over previous
#include <cuda_runtime.h>
#include <cuda_bf16.h>
#include <cstdint>
#include <math.h>

#define B_   4
#define S_   4096
#define D_   512
#define H_   8
#define KD_  64
#define R_   256
#define M_   (B_*S_)       // 16384 rows of x
#define ROWS_ (M_*H_)      // 131072 (b,s,h) rows
#define EPS_ 1e-3f
#define SCALE_ 0.125f      // 1/sqrt(64)
#define NSPLIT 16

typedef unsigned long long ull;

// ---- packed f32x2 helpers ----
__device__ __forceinline__ ull pk2(float a, float b) {
    ull r; asm("mov.b64 %0, {%1,%2};" : "=l"(r) : "f"(a), "f"(b)); return r;
}
__device__ __forceinline__ void fma2(ull& d, ull a, ull b) {
    asm("fma.rn.f32x2 %0, %1, %2, %0;" : "+l"(d) : "l"(a), "l"(b));
}
__device__ __forceinline__ float2 up2(ull v) {
    float2 f; asm("mov.b64 {%0,%1}, %2;" : "=f"(f.x), "=f"(f.y) : "l"(v)); return f;
}

// ---- mma.sync / ldmatrix helpers (baseline sm_80+ PTX; valid on sm_103) ----
__device__ __forceinline__ uint32_t smem_u32(const void* p) {
    uint32_t a;
    asm("{ .reg .u64 t; cvta.to.shared.u64 t, %1; cvt.u32.u64 %0, t; }" : "=r"(a) : "l"(p));
    return a;
}
__device__ __forceinline__ void ldsm4(uint32_t& r0, uint32_t& r1, uint32_t& r2, uint32_t& r3,
                                      uint32_t addr) {
    asm volatile("ldmatrix.sync.aligned.m8n8.x4.shared.b16 {%0,%1,%2,%3}, [%4];"
                 : "=r"(r0), "=r"(r1), "=r"(r2), "=r"(r3) : "r"(addr));
}
__device__ __forceinline__ void mma16816(float* c, const uint32_t* a, const uint32_t* b) {
    asm volatile("mma.sync.aligned.m16n8k16.row.col.f32.bf16.bf16.f32 "
                 "{%0,%1,%2,%3}, {%4,%5,%6,%7}, {%8,%9}, {%0,%1,%2,%3};"
                 : "+f"(c[0]), "+f"(c[1]), "+f"(c[2]), "+f"(c[3])
                 : "r"(a[0]), "r"(a[1]), "r"(a[2]), "r"(a[3]), "r"(b[0]), "r"(b[1]));
}

// ---------------- scratch ----------------
__device__ float g_q[M_*D_];
__device__ float g_k[M_*D_];
__device__ float g_v[M_*D_];
__device__ float g_qf[(size_t)ROWS_*R_];
__device__ float g_kf[(size_t)ROWS_*R_];
__device__ float g_kvp[B_*H_*NSPLIT*R_*KD_];
__device__ float g_ksump[B_*H_*NSPLIT*R_];
__device__ float g_kv[B_*H_*R_*KD_];
__device__ float g_ksum[B_*H_*R_];
__device__ float g_attn[M_*D_];
__device__ __nv_bfloat16 g_xh[M_*D_];
__device__ __nv_bfloat16 g_xl[M_*D_];
__device__ __nv_bfloat16 g_ah[M_*D_];
__device__ __nv_bfloat16 g_al[M_*D_];
__device__ __nv_bfloat16 g_wh[4][D_*D_];   // transposed weights hi: [n][k]
__device__ __nv_bfloat16 g_wl[4][D_*D_];   // transposed weights lo

// ---------------- fp32 -> bf16 hi/lo split (row-major passthrough) ----------------
__global__ void split_kernel(const float4* __restrict__ src,
                             uint2* __restrict__ hi, uint2* __restrict__ lo) {
    int i = blockIdx.x*256 + threadIdx.x;   // over M_*D_/4
    float4 v = src[i];
    __nv_bfloat16 h0 = __float2bfloat16(v.x), h1 = __float2bfloat16(v.y);
    __nv_bfloat16 h2 = __float2bfloat16(v.z), h3 = __float2bfloat16(v.w);
    __nv_bfloat16 l0 = __float2bfloat16(v.x - __bfloat162float(h0));
    __nv_bfloat16 l1 = __float2bfloat16(v.y - __bfloat162float(h1));
    __nv_bfloat16 l2 = __float2bfloat16(v.z - __bfloat162float(h2));
    __nv_bfloat16 l3 = __float2bfloat16(v.w - __bfloat162float(h3));
    __nv_bfloat162 hp0; hp0.x = h0; hp0.y = h1;
    __nv_bfloat162 hp1; hp1.x = h2; hp1.y = h3;
    __nv_bfloat162 lp0; lp0.x = l0; lp0.y = l1;
    __nv_bfloat162 lp1; lp1.x = l2; lp1.y = l3;
    hi[i] = make_uint2(*(uint32_t*)&hp0, *(uint32_t*)&hp1);
    lo[i] = make_uint2(*(uint32_t*)&lp0, *(uint32_t*)&lp1);
}

// ---------------- W[k][n] -> Wt[n][k] bf16 hi/lo (transpose + split) ----------------
__global__ void wsplit_kernel(const float* __restrict__ W,
                              __nv_bfloat16* __restrict__ Th, __nv_bfloat16* __restrict__ Tl) {
    __shared__ float tile[32][33];
    int n0 = blockIdx.x*32, k0 = blockIdx.y*32;
    int tx = threadIdx.x, ty = threadIdx.y;    // (32, 8)
    #pragma unroll
    for (int j = 0; j < 32; j += 8)
        tile[ty+j][tx] = W[(size_t)(k0+ty+j)*D_ + n0+tx];
    __syncthreads();
    #pragma unroll
    for (int j = 0; j < 32; j += 8) {
        float v = tile[tx][ty+j];              // = W[k0+tx][n0+ty+j]
        __nv_bfloat16 h = __float2bfloat16(v);
        __nv_bfloat16 l = __float2bfloat16(v - __bfloat162float(h));
        Th[(size_t)(n0+ty+j)*D_ + k0+tx] = h;
        Tl[(size_t)(n0+ty+j)*D_ + k0+tx] = l;
    }
}

// ---------------- HMMA bf16-split GEMM: C[M,512] = A[M,512] @ W[512,512] (+bias) -------
// A pre-split row-major [m][k]; W pre-split transposed [n][k] (= B col-major for mma).
// Block tile 128x128, BK=64, 8 warps (4m x 2n), warp tile 32x64.
// 3 passes per k16: Ah*Bh + Ah*Bl + Al*Bh. fp32 accumulators.
#define AST 72                         // padded smem row stride (bf16 units), conflict-free
#define MMSM (4*128*AST*2)             // 73728 B: Ah, Al, Bh, Bl tiles
__global__ void __launch_bounds__(256) mma_gemm(
        const __nv_bfloat16* __restrict__ Ah_g, const __nv_bfloat16* __restrict__ Al_g,
        const __nv_bfloat16* __restrict__ Bh_g, const __nv_bfloat16* __restrict__ Bl_g,
        float* __restrict__ C, const float* __restrict__ bias) {
    extern __shared__ __nv_bfloat16 sm[];
    __nv_bfloat16* sAh = sm;
    __nv_bfloat16* sAl = sm + 128*AST;
    __nv_bfloat16* sBh = sm + 2*128*AST;
    __nv_bfloat16* sBl = sm + 3*128*AST;
    int t = threadIdx.x, lane = t & 31, w = t >> 5;
    int wm = w & 3, wn = w >> 2;
    int n0 = blockIdx.x * 128;
    size_t m0 = (size_t)blockIdx.y * 128;

    float acc[2][8][4] = {};

    uint32_t sAh_b = smem_u32(sAh), sAl_b = smem_u32(sAl);
    uint32_t sBh_b = smem_u32(sBh), sBl_b = smem_u32(sBl);

    // per-lane ldmatrix row/col components
    int a_row = wm*32 + (lane & 15);          // + mt*16
    int a_col8 = (lane >> 4) * 8;             // + k16*16
    int b_row = wn*64 + ((lane >> 4) & 1)*8 + (lane & 7);   // + p*16
    int b_col8 = ((lane >> 3) & 1) * 8;       // + k16*16

    for (int kb = 0; kb < D_; kb += 64) {
        // ---- stage all 4 tiles (128 rows x 64 bf16 each = 1024 uint4 per tile) ----
        #pragma unroll
        for (int j = 0; j < 4; j++) {
            int idx = t + j*256;              // 0..1023
            int row = idx >> 3, c8 = idx & 7;
            *(uint4*)(sAh + row*AST + c8*8) = *(const uint4*)(Ah_g + (m0+row)*D_ + kb + c8*8);
            *(uint4*)(sAl + row*AST + c8*8) = *(const uint4*)(Al_g + (m0+row)*D_ + kb + c8*8);
            *(uint4*)(sBh + row*AST + c8*8) = *(const uint4*)(Bh_g + (size_t)(n0+row)*D_ + kb + c8*8);
            *(uint4*)(sBl + row*AST + c8*8) = *(const uint4*)(Bl_g + (size_t)(n0+row)*D_ + kb + c8*8);
        }
        __syncthreads();

        #pragma unroll
        for (int k16 = 0; k16 < 4; k16++) {
            int ak = k16*16 + a_col8;
            int bk = k16*16 + b_col8;
            #pragma unroll
            for (int pass = 0; pass < 3; pass++) {
                uint32_t aBase = (pass == 2) ? sAl_b : sAh_b;
                uint32_t bBase = (pass == 1) ? sBl_b : sBh_b;
                uint32_t aF[2][4];
                #pragma unroll
                for (int mt = 0; mt < 2; mt++) {
                    uint32_t addr = aBase + (uint32_t)((a_row + mt*16)*AST + ak)*2;
                    ldsm4(aF[mt][0], aF[mt][1], aF[mt][2], aF[mt][3], addr);
                }
                uint32_t bF[8][2];
                #pragma unroll
                for (int p = 0; p < 4; p++) {
                    uint32_t addr = bBase + (uint32_t)((b_row + p*16)*AST + bk)*2;
                    uint32_t r0, r1, r2, r3;
                    ldsm4(r0, r1, r2, r3, addr);
                    bF[2*p][0]   = r0; bF[2*p][1]   = r1;
                    bF[2*p+1][0] = r2; bF[2*p+1][1] = r3;
                }
                #pragma unroll
                for (int mt = 0; mt < 2; mt++)
                    #pragma unroll
                    for (int nt = 0; nt < 8; nt++)
                        mma16816(acc[mt][nt], aF[mt], bF[nt]);
            }
        }
        __syncthreads();
    }

    // ---- epilogue ----
    int g = lane >> 2;
    int cl = (lane & 3) * 2;
    #pragma unroll
    for (int mt = 0; mt < 2; mt++) {
        #pragma unroll
        for (int nt = 0; nt < 8; nt++) {
            int col = n0 + wn*64 + nt*8 + cl;
            float bx = 0.f, by = 0.f;
            if (bias) { bx = bias[col]; by = bias[col+1]; }
            size_t r0 = m0 + wm*32 + mt*16 + g;
            *(float2*)(C + r0*D_ + col)       = make_float2(acc[mt][nt][0] + bx, acc[mt][nt][1] + by);
            *(float2*)(C + (r0 + 8)*D_ + col) = make_float2(acc[mt][nt][2] + bx, acc[mt][nt][3] + by);
        }
    }
}

// ---------------- feature kernel (packed f32x2, 8x8 microtile) ----------------
__global__ void __launch_bounds__(256) feat_kernel(
        const float* __restrict__ T, const float* __restrict__ rf,
        float* __restrict__ outF) {
    __shared__ float As[16][64];
    __shared__ float Bs[16][256];
    int t = threadIdx.x;
    int tx = t & 31;
    int ty = t >> 5;
    size_t m0 = (size_t)blockIdx.x * 64;
    ull acc[8][4] = {};
    int arow = t >> 2, ac = t & 3;

    for (int kb = 0; kb < KD_; kb += 16) {
        float4 a4 = *(const float4*)(T + (m0 + arow)*KD_ + kb + ac*4);
        As[ac*4+0][arow] = a4.x;
        As[ac*4+1][arow] = a4.y;
        As[ac*4+2][arow] = a4.z;
        As[ac*4+3][arow] = a4.w;
        #pragma unroll
        for (int j = 0; j < 4; j++) {
            int idx = t + 256*j;
            int r = idx >> 2, dq = idx & 3;
            float4 b4 = *(const float4*)(rf + r*KD_ + kb + dq*4);
            Bs[dq*4+0][r] = b4.x;
            Bs[dq*4+1][r] = b4.y;
            Bs[dq*4+2][r] = b4.z;
            Bs[dq*4+3][r] = b4.w;
        }
        __syncthreads();
        #pragma unroll
        for (int k = 0; k < 16; k++) {
            float4 a0 = *(float4*)&As[k][ty*8];
            float4 a1 = *(float4*)&As[k][ty*8+4];
            float4 b0 = *(float4*)&Bs[k][tx*8];
            float4 b1 = *(float4*)&Bs[k][tx*8+4];
            ull bp[4] = {pk2(b0.x,b0.y), pk2(b0.z,b0.w), pk2(b1.x,b1.y), pk2(b1.z,b1.w)};
            float av[8] = {a0.x,a0.y,a0.z,a0.w,a1.x,a1.y,a1.z,a1.w};
            #pragma unroll
            for (int i = 0; i < 8; i++) {
                ull aa = pk2(av[i], av[i]);
                #pragma unroll
                for (int j = 0; j < 4; j++)
                    fma2(acc[i][j], aa, bp[j]);
            }
        }
        __syncthreads();
    }
    #pragma unroll
    for (int i = 0; i < 8; i++) {
        float2 p0 = up2(acc[i][0]), p1 = up2(acc[i][1]);
        float2 p2 = up2(acc[i][2]), p3 = up2(acc[i][3]);
        float v[8] = {p0.x,p0.y,p1.x,p1.y,p2.x,p2.y,p3.x,p3.y};
        float mx = -1e30f;
        #pragma unroll
        for (int j = 0; j < 8; j++) { v[j] *= SCALE_; mx = fmaxf(mx, v[j]); }
        #pragma unroll
        for (int off = 16; off >= 1; off >>= 1)
            mx = fmaxf(mx, __shfl_xor_sync(0xffffffffu, mx, off));
        float4 o0, o1;
        o0.x = __expf(v[0]-mx)+EPS_; o0.y = __expf(v[1]-mx)+EPS_;
        o0.z = __expf(v[2]-mx)+EPS_; o0.w = __expf(v[3]-mx)+EPS_;
        o1.x = __expf(v[4]-mx)+EPS_; o1.y = __expf(v[5]-mx)+EPS_;
        o1.z = __expf(v[6]-mx)+EPS_; o1.w = __expf(v[7]-mx)+EPS_;
        size_t m = m0 + ty*8 + i;
        float4* dst = (float4*)(outF + m*R_ + tx*8);
        dst[0] = o0;
        dst[1] = o1;
    }
}

// ---------------- kv partial sums ----------------
__global__ void kvsum_kernel(const float* __restrict__ kf, const float* __restrict__ v,
                             float* __restrict__ kvp, float* __restrict__ ksump) {
    __shared__ float kfs[32*256];
    __shared__ float vs[32*64];
    int bh = blockIdx.x, sp = blockIdx.y;
    int b = bh >> 3, h = bh & 7;
    int t = threadIdx.x, tx = t & 15, ty = t >> 4;
    ull acc[8][4] = {};
    float ks = 0.f;
    int sbase = sp*256;
    for (int s0 = 0; s0 < 256; s0 += 32) {
        #pragma unroll
        for (int j = 0; j < 8; j++) {
            int idx = t + 256*j;
            int si = idx >> 6, c = idx & 63;
            size_t row = (size_t)(b*S_ + sbase + s0 + si)*H_ + h;
            ((float4*)kfs)[idx] = ((const float4*)(kf + row*R_))[c];
        }
        #pragma unroll
        for (int j = 0; j < 2; j++) {
            int idx = t + 256*j;
            int si = idx >> 4, c = idx & 15;
            size_t row = (size_t)(b*S_ + sbase + s0 + si)*H_ + h;
            ((float4*)vs)[idx] = ((const float4*)(v + row*KD_))[c];
        }
        __syncthreads();
        for (int si = 0; si < 32; si++) {
            ks += kfs[si*256 + t];
            float4 v4 = ((float4*)(vs + si*64))[tx];
            ull vd[4] = {pk2(v4.x,v4.x), pk2(v4.y,v4.y), pk2(v4.z,v4.z), pk2(v4.w,v4.w)};
            const float2* arow = (const float2*)(kfs + si*256 + ty*16);
            #pragma unroll
            for (int i2 = 0; i2 < 8; i2++) {
                float2 ap = arow[i2];
                ull aa = pk2(ap.x, ap.y);
                #pragma unroll
                for (int j = 0; j < 4; j++)
                    fma2(acc[i2][j], aa, vd[j]);
            }
        }
        __syncthreads();
    }
    size_t base = ((size_t)bh*NSPLIT + sp)*R_;
    ksump[base + t] = ks;
    #pragma unroll
    for (int i2 = 0; i2 < 8; i2++) {
        float2 c0 = up2(acc[i2][0]), c1 = up2(acc[i2][1]);
        float2 c2 = up2(acc[i2][2]), c3 = up2(acc[i2][3]);
        int r0 = ty*16 + 2*i2;
        *(float4*)(kvp + (base + r0)*KD_ + tx*4)     = make_float4(c0.x, c1.x, c2.x, c3.x);
        *(float4*)(kvp + (base + r0 + 1)*KD_ + tx*4) = make_float4(c0.y, c1.y, c2.y, c3.y);
    }
}

// ---------------- deterministic split reduce ----------------
__global__ void reduce_kernel(const float* __restrict__ kvp, const float* __restrict__ ksump,
                              float* __restrict__ kv, float* __restrict__ ksum) {
    int idx = blockIdx.x*256 + threadIdx.x;
    const int NKV = B_*H_*R_*KD_;
    if (idx < NKV) {
        int bh = idx >> 14;
        int rd = idx & 16383;
        float s = 0.f;
        #pragma unroll
        for (int sp = 0; sp < NSPLIT; sp++)
            s += kvp[((size_t)(bh*NSPLIT + sp) << 14) + rd];
        kv[idx] = s;
    } else {
        int j = idx - NKV;
        if (j < B_*H_*R_) {
            int bh = j >> 8, r = j & 255;
            float s = 0.f;
            #pragma unroll
            for (int sp = 0; sp < NSPLIT; sp++)
                s += ksump[(bh*NSPLIT + sp)*R_ + r];
            ksum[j] = s;
        }
    }
}

// ---------------- attn ----------------
__global__ void attn_kernel(const float* __restrict__ qf, const float* __restrict__ kv,
                            const float* __restrict__ ksum, float* __restrict__ attn) {
    __shared__ float qfs[64*32];
    __shared__ float kvs[32*64];
    __shared__ float kss[256];
    int bh = blockIdx.x, b = bh >> 3, h = bh & 7;
    int s0 = blockIdx.y * 64;
    int t = threadIdx.x, tx = t & 15, ty = t >> 4;
    kss[t] = ksum[bh*R_ + t];
    ull acc[4][2] = {};
    float den[4] = {};
    for (int rb = 0; rb < R_; rb += 32) {
        #pragma unroll
        for (int j = 0; j < 2; j++) {
            int idx = t + 256*j;
            int row = idx >> 3, c = idx & 7;
            size_t g = ((size_t)(b*S_ + s0 + row)*H_ + h)*R_ + rb;
            ((float4*)qfs)[idx] = ((const float4*)(qf + g))[c];
        }
        #pragma unroll
        for (int j = 0; j < 2; j++) {
            int idx = t + 256*j;
            int k = idx >> 4, c = idx & 15;
            ((float4*)kvs)[idx] = ((const float4*)(kv + ((size_t)bh*R_ + rb + k)*KD_))[c];
        }
        __syncthreads();
        #pragma unroll
        for (int k = 0; k < 32; k++) {
            float4 b4 = ((float4*)(kvs + k*64))[tx];
            ull bp0 = pk2(b4.x, b4.y), bp1 = pk2(b4.z, b4.w);
            float ksv = kss[rb + k];
            #pragma unroll
            for (int i = 0; i < 4; i++) {
                float a = qfs[(ty*4+i)*32 + k];
                den[i] += a*ksv;
                ull aa = pk2(a, a);
                fma2(acc[i][0], aa, bp0);
                fma2(acc[i][1], aa, bp1);
            }
        }
        __syncthreads();
    }
    #pragma unroll
    for (int i = 0; i < 4; i++) {
        int s = s0 + ty*4 + i;
        float inv = 1.0f / (den[i] + EPS_);
        float2 c0 = up2(acc[i][0]), c1 = up2(acc[i][1]);
        float4 o = make_float4(c0.x*inv, c0.y*inv, c1.x*inv, c1.y*inv);
        *(float4*)(attn + (size_t)(b*S_ + s)*D_ + h*KD_ + tx*4) = o;
    }
}

// ---------------- launch ----------------
extern "C" void kernel_launch(void* const* d_in, const int* in_sizes, int n_in,
                              void* d_out, int out_size) {
    const float* x  = (const float*)d_in[0];
    const float* Wq = (const float*)d_in[1];
    const float* Wk = (const float*)d_in[2];
    const float* Wv = (const float*)d_in[3];
    const float* rf = (const float*)d_in[4];
    const float* Wo = (const float*)d_in[5];
    const float* bo = (const float*)d_in[6];
    float* out = (float*)d_out;

    float *pq, *pk, *pv, *pqf, *pkf, *pkvp, *pksp, *pkv, *pks, *pattn;
    __nv_bfloat16 *pxh, *pxl, *pah, *pal, *pwh, *pwl;
    cudaGetSymbolAddress((void**)&pq,   g_q);
    cudaGetSymbolAddress((void**)&pk,   g_k);
    cudaGetSymbolAddress((void**)&pv,   g_v);
    cudaGetSymbolAddress((void**)&pqf,  g_qf);
    cudaGetSymbolAddress((void**)&pkf,  g_kf);
    cudaGetSymbolAddress((void**)&pkvp, g_kvp);
    cudaGetSymbolAddress((void**)&pksp, g_ksump);
    cudaGetSymbolAddress((void**)&pkv,  g_kv);
    cudaGetSymbolAddress((void**)&pks,  g_ksum);
    cudaGetSymbolAddress((void**)&pattn,g_attn);
    cudaGetSymbolAddress((void**)&pxh,  g_xh);
    cudaGetSymbolAddress((void**)&pxl,  g_xl);
    cudaGetSymbolAddress((void**)&pah,  g_ah);
    cudaGetSymbolAddress((void**)&pal,  g_al);
    cudaGetSymbolAddress((void**)&pwh,  g_wh);
    cudaGetSymbolAddress((void**)&pwl,  g_wl);

    cudaFuncSetAttribute(mma_gemm, cudaFuncAttributeMaxDynamicSharedMemorySize, MMSM);

    const int WSZ = D_*D_;
    dim3 wgrid(16, 16), wblk(32, 8);
    wsplit_kernel<<<wgrid, wblk>>>(Wq, pwh + 0*WSZ, pwl + 0*WSZ);
    wsplit_kernel<<<wgrid, wblk>>>(Wk, pwh + 1*WSZ, pwl + 1*WSZ);
    wsplit_kernel<<<wgrid, wblk>>>(Wv, pwh + 2*WSZ, pwl + 2*WSZ);
    wsplit_kernel<<<wgrid, wblk>>>(Wo, pwh + 3*WSZ, pwl + 3*WSZ);

    split_kernel<<<M_*D_/4/256, 256>>>((const float4*)x, (uint2*)pxh, (uint2*)pxl);

    dim3 tg(D_/128, M_/128);   // (4, 128)
    mma_gemm<<<tg, 256, MMSM>>>(pxh, pxl, pwh + 0*WSZ, pwl + 0*WSZ, pq, nullptr);
    mma_gemm<<<tg, 256, MMSM>>>(pxh, pxl, pwh + 1*WSZ, pwl + 1*WSZ, pk, nullptr);
    mma_gemm<<<tg, 256, MMSM>>>(pxh, pxl, pwh + 2*WSZ, pwl + 2*WSZ, pv, nullptr);

    feat_kernel<<<ROWS_/64, 256>>>(pq, rf, pqf);
    feat_kernel<<<ROWS_/64, 256>>>(pk, rf, pkf);

    kvsum_kernel<<<dim3(B_*H_, NSPLIT), 256>>>(pkf, pv, pkvp, pksp);
    reduce_kernel<<<(B_*H_*R_*KD_ + B_*H_*R_ + 255)/256, 256>>>(pkvp, pksp, pkv, pks);

    attn_kernel<<<dim3(B_*H_, S_/64), 256>>>(pqf, pkv, pks, pattn);

    split_kernel<<<M_*D_/4/256, 256>>>((const float4*)pattn, (uint2*)pah, (uint2*)pal);
    mma_gemm<<<tg, 256, MMSM>>>(pah, pal, pwh + 3*WSZ, pwl + 3*WSZ, out, bo);
}

// round 7
// speedup vs baseline: 3.0177x; 1.0336x over previous
#include <cuda_runtime.h>
#include <cuda_bf16.h>
#include <cstdint>
#include <math.h>

#define B_   4
#define S_   4096
#define D_   512
#define H_   8
#define KD_  64
#define R_   256
#define M_   (B_*S_)       // 16384 rows of x
#define ROWS_ (M_*H_)      // 131072 (b,s,h) rows
#define EPS_ 1e-3f
#define SCALE_ 0.125f      // 1/sqrt(64)
#define NSPLIT 16

typedef unsigned long long ull;

// ---- packed f32x2 helpers ----
__device__ __forceinline__ ull pk2(float a, float b) {
    ull r; asm("mov.b64 %0, {%1,%2};" : "=l"(r) : "f"(a), "f"(b)); return r;
}
__device__ __forceinline__ void fma2(ull& d, ull a, ull b) {
    asm("fma.rn.f32x2 %0, %1, %2, %0;" : "+l"(d) : "l"(a), "l"(b));
}
__device__ __forceinline__ float2 up2(ull v) {
    float2 f; asm("mov.b64 {%0,%1}, %2;" : "=f"(f.x), "=f"(f.y) : "l"(v)); return f;
}

// ---- mma.sync / ldmatrix / cp.async helpers (baseline sm_80+ PTX) ----
__device__ __forceinline__ uint32_t smem_u32(const void* p) {
    uint32_t a;
    asm("{ .reg .u64 t; cvta.to.shared.u64 t, %1; cvt.u32.u64 %0, t; }" : "=r"(a) : "l"(p));
    return a;
}
__device__ __forceinline__ void ldsm4(uint32_t& r0, uint32_t& r1, uint32_t& r2, uint32_t& r3,
                                      uint32_t addr) {
    asm volatile("ldmatrix.sync.aligned.m8n8.x4.shared.b16 {%0,%1,%2,%3}, [%4];"
                 : "=r"(r0), "=r"(r1), "=r"(r2), "=r"(r3) : "r"(addr));
}
__device__ __forceinline__ void mma16816(float* c, const uint32_t* a, const uint32_t* b) {
    asm volatile("mma.sync.aligned.m16n8k16.row.col.f32.bf16.bf16.f32 "
                 "{%0,%1,%2,%3}, {%4,%5,%6,%7}, {%8,%9}, {%0,%1,%2,%3};"
                 : "+f"(c[0]), "+f"(c[1]), "+f"(c[2]), "+f"(c[3])
                 : "r"(a[0]), "r"(a[1]), "r"(a[2]), "r"(a[3]), "r"(b[0]), "r"(b[1]));
}
__device__ __forceinline__ void cpa16(uint32_t dst, const void* src) {
    asm volatile("cp.async.cg.shared.global [%0], [%1], 16;" :: "r"(dst), "l"(src));
}
#define CPA_COMMIT() asm volatile("cp.async.commit_group;" ::: "memory")
#define CPA_WAIT(n)  asm volatile("cp.async.wait_group %0;" :: "n"(n) : "memory")

// ---------------- scratch ----------------
__device__ float g_q[M_*D_];
__device__ float g_k[M_*D_];
__device__ float g_v[M_*D_];
__device__ float g_qf[(size_t)ROWS_*R_];
__device__ float g_kf[(size_t)ROWS_*R_];
__device__ float g_kvp[B_*H_*NSPLIT*R_*KD_];
__device__ float g_ksump[B_*H_*NSPLIT*R_];
__device__ float g_kv[B_*H_*R_*KD_];
__device__ float g_ksum[B_*H_*R_];
__device__ float g_attn[M_*D_];
__device__ __nv_bfloat16 g_xh[M_*D_];
__device__ __nv_bfloat16 g_xl[M_*D_];
__device__ __nv_bfloat16 g_ah[M_*D_];
__device__ __nv_bfloat16 g_al[M_*D_];
__device__ __nv_bfloat16 g_wh[4][D_*D_];   // transposed weights hi: [n][k]
__device__ __nv_bfloat16 g_wl[4][D_*D_];   // transposed weights lo

// ---------------- fp32 -> bf16 hi/lo split ----------------
__global__ void split_kernel(const float4* __restrict__ src,
                             uint2* __restrict__ hi, uint2* __restrict__ lo) {
    int i = blockIdx.x*256 + threadIdx.x;
    float4 v = src[i];
    __nv_bfloat16 h0 = __float2bfloat16(v.x), h1 = __float2bfloat16(v.y);
    __nv_bfloat16 h2 = __float2bfloat16(v.z), h3 = __float2bfloat16(v.w);
    __nv_bfloat16 l0 = __float2bfloat16(v.x - __bfloat162float(h0));
    __nv_bfloat16 l1 = __float2bfloat16(v.y - __bfloat162float(h1));
    __nv_bfloat16 l2 = __float2bfloat16(v.z - __bfloat162float(h2));
    __nv_bfloat16 l3 = __float2bfloat16(v.w - __bfloat162float(h3));
    __nv_bfloat162 hp0; hp0.x = h0; hp0.y = h1;
    __nv_bfloat162 hp1; hp1.x = h2; hp1.y = h3;
    __nv_bfloat162 lp0; lp0.x = l0; lp0.y = l1;
    __nv_bfloat162 lp1; lp1.x = l2; lp1.y = l3;
    hi[i] = make_uint2(*(uint32_t*)&hp0, *(uint32_t*)&hp1);
    lo[i] = make_uint2(*(uint32_t*)&lp0, *(uint32_t*)&lp1);
}

// ---------------- W[k][n] -> Wt[n][k] bf16 hi/lo (transpose + split) ----------------
__global__ void wsplit_kernel(const float* __restrict__ W,
                              __nv_bfloat16* __restrict__ Th, __nv_bfloat16* __restrict__ Tl) {
    __shared__ float tile[32][33];
    int n0 = blockIdx.x*32, k0 = blockIdx.y*32;
    int tx = threadIdx.x, ty = threadIdx.y;    // (32, 8)
    #pragma unroll
    for (int j = 0; j < 32; j += 8)
        tile[ty+j][tx] = W[(size_t)(k0+ty+j)*D_ + n0+tx];
    __syncthreads();
    #pragma unroll
    for (int j = 0; j < 32; j += 8) {
        float v = tile[tx][ty+j];
        __nv_bfloat16 h = __float2bfloat16(v);
        __nv_bfloat16 l = __float2bfloat16(v - __bfloat162float(h));
        Th[(size_t)(n0+ty+j)*D_ + k0+tx] = h;
        Tl[(size_t)(n0+ty+j)*D_ + k0+tx] = l;
    }
}

// ---------------- HMMA bf16-split GEMM, double-buffered cp.async pipeline -------------
// C[M,512] = A[M,512] @ W[512,512] (+bias). A split row-major [m][k]; W split [n][k].
// Block tile 128x128, BK=64, 8 warps (4m x 2n), warp tile 32x64.
// 3 passes per k16: Ah*Bh + Ah*Bl + Al*Bh. fp32 accumulators.
#define AST 72                          // padded smem row stride (bf16), 144 B (16B-aligned)
#define TILE_BYTES (128*AST*2)          // 18432 per tile
#define BUF_BYTES  (4*TILE_BYTES)       // 73728: Ah, Al, Bh, Bl
#define MMSM (2*BUF_BYTES)              // 147456: double buffer
__global__ void __launch_bounds__(256) mma_gemm(
        const __nv_bfloat16* __restrict__ Ah_g, const __nv_bfloat16* __restrict__ Al_g,
        const __nv_bfloat16* __restrict__ Bh_g, const __nv_bfloat16* __restrict__ Bl_g,
        float* __restrict__ C, const float* __restrict__ bias) {
    extern __shared__ __nv_bfloat16 sm[];
    uint32_t sbase = smem_u32(sm);
    int t = threadIdx.x, lane = t & 31, w = t >> 5;
    int wm = w & 3, wn = w >> 2;
    int n0 = blockIdx.x * 128;
    size_t m0 = (size_t)blockIdx.y * 128;

    float acc[2][8][4] = {};

    // per-lane ldmatrix row/col components
    int a_row = wm*32 + (lane & 15);
    int a_col8 = (lane >> 4) * 8;
    int b_row = wn*64 + ((lane >> 4) & 1)*8 + (lane & 7);
    int b_col8 = ((lane >> 3) & 1) * 8;

    // this thread's staging slot: 4 uint4 per tile
    int srow[4], sc8[4];
    #pragma unroll
    for (int j = 0; j < 4; j++) { int idx = t + j*256; srow[j] = idx >> 3; sc8[j] = idx & 7; }

    // ---- stage chunk 0 into buffer 0 ----
    {
        uint32_t bb = sbase;
        #pragma unroll
        for (int j = 0; j < 4; j++) {
            uint32_t off = (uint32_t)(srow[j]*AST + sc8[j]*8)*2;
            cpa16(bb + 0*TILE_BYTES + off, Ah_g + (m0+srow[j])*D_ + 0 + sc8[j]*8);
            cpa16(bb + 1*TILE_BYTES + off, Al_g + (m0+srow[j])*D_ + 0 + sc8[j]*8);
            cpa16(bb + 2*TILE_BYTES + off, Bh_g + (size_t)(n0+srow[j])*D_ + 0 + sc8[j]*8);
            cpa16(bb + 3*TILE_BYTES + off, Bl_g + (size_t)(n0+srow[j])*D_ + 0 + sc8[j]*8);
        }
        CPA_COMMIT();
    }

    for (int c = 0; c < 8; c++) {
        int buf = c & 1;
        // prefetch next chunk into the other buffer
        if (c < 7) {
            int kb = (c+1)*64;
            uint32_t bb = sbase + (buf^1)*BUF_BYTES;
            #pragma unroll
            for (int j = 0; j < 4; j++) {
                uint32_t off = (uint32_t)(srow[j]*AST + sc8[j]*8)*2;
                cpa16(bb + 0*TILE_BYTES + off, Ah_g + (m0+srow[j])*D_ + kb + sc8[j]*8);
                cpa16(bb + 1*TILE_BYTES + off, Al_g + (m0+srow[j])*D_ + kb + sc8[j]*8);
                cpa16(bb + 2*TILE_BYTES + off, Bh_g + (size_t)(n0+srow[j])*D_ + kb + sc8[j]*8);
                cpa16(bb + 3*TILE_BYTES + off, Bl_g + (size_t)(n0+srow[j])*D_ + kb + sc8[j]*8);
            }
            CPA_COMMIT();
            CPA_WAIT(1);      // current chunk's group done; prefetch may be in flight
        } else {
            CPA_WAIT(0);
        }
        __syncthreads();

        uint32_t bb = sbase + buf*BUF_BYTES;
        uint32_t sAh_b = bb, sAl_b = bb + TILE_BYTES;
        uint32_t sBh_b = bb + 2*TILE_BYTES, sBl_b = bb + 3*TILE_BYTES;

        #pragma unroll
        for (int k16 = 0; k16 < 4; k16++) {
            int ak = k16*16 + a_col8;
            int bk = k16*16 + b_col8;
            #pragma unroll
            for (int pass = 0; pass < 3; pass++) {
                uint32_t aBase = (pass == 2) ? sAl_b : sAh_b;
                uint32_t bBase = (pass == 1) ? sBl_b : sBh_b;
                uint32_t aF[2][4];
                #pragma unroll
                for (int mt = 0; mt < 2; mt++) {
                    uint32_t addr = aBase + (uint32_t)((a_row + mt*16)*AST + ak)*2;
                    ldsm4(aF[mt][0], aF[mt][1], aF[mt][2], aF[mt][3], addr);
                }
                uint32_t bF[8][2];
                #pragma unroll
                for (int p = 0; p < 4; p++) {
                    uint32_t addr = bBase + (uint32_t)((b_row + p*16)*AST + bk)*2;
                    uint32_t r0, r1, r2, r3;
                    ldsm4(r0, r1, r2, r3, addr);
                    bF[2*p][0]   = r0; bF[2*p][1]   = r1;
                    bF[2*p+1][0] = r2; bF[2*p+1][1] = r3;
                }
                #pragma unroll
                for (int mt = 0; mt < 2; mt++)
                    #pragma unroll
                    for (int nt = 0; nt < 8; nt++)
                        mma16816(acc[mt][nt], aF[mt], bF[nt]);
            }
        }
        __syncthreads();   // all warps done reading buf before its cp.async overwrite
    }

    // ---- epilogue ----
    int g = lane >> 2;
    int cl = (lane & 3) * 2;
    #pragma unroll
    for (int mt = 0; mt < 2; mt++) {
        #pragma unroll
        for (int nt = 0; nt < 8; nt++) {
            int col = n0 + wn*64 + nt*8 + cl;
            float bx = 0.f, by = 0.f;
            if (bias) { bx = bias[col]; by = bias[col+1]; }
            size_t r0 = m0 + wm*32 + mt*16 + g;
            *(float2*)(C + r0*D_ + col)       = make_float2(acc[mt][nt][0] + bx, acc[mt][nt][1] + by);
            *(float2*)(C + (r0 + 8)*D_ + col) = make_float2(acc[mt][nt][2] + bx, acc[mt][nt][3] + by);
        }
    }
}

// ---------------- feature kernel (packed f32x2, 8x8 microtile) ----------------
__global__ void __launch_bounds__(256) feat_kernel(
        const float* __restrict__ T, const float* __restrict__ rf,
        float* __restrict__ outF) {
    __shared__ float As[16][64];
    __shared__ float Bs[16][256];
    int t = threadIdx.x;
    int tx = t & 31;
    int ty = t >> 5;
    size_t m0 = (size_t)blockIdx.x * 64;
    ull acc[8][4] = {};
    int arow = t >> 2, ac = t & 3;

    for (int kb = 0; kb < KD_; kb += 16) {
        float4 a4 = *(const float4*)(T + (m0 + arow)*KD_ + kb + ac*4);
        As[ac*4+0][arow] = a4.x;
        As[ac*4+1][arow] = a4.y;
        As[ac*4+2][arow] = a4.z;
        As[ac*4+3][arow] = a4.w;
        #pragma unroll
        for (int j = 0; j < 4; j++) {
            int idx = t + 256*j;
            int r = idx >> 2, dq = idx & 3;
            float4 b4 = *(const float4*)(rf + r*KD_ + kb + dq*4);
            Bs[dq*4+0][r] = b4.x;
            Bs[dq*4+1][r] = b4.y;
            Bs[dq*4+2][r] = b4.z;
            Bs[dq*4+3][r] = b4.w;
        }
        __syncthreads();
        #pragma unroll
        for (int k = 0; k < 16; k++) {
            float4 a0 = *(float4*)&As[k][ty*8];
            float4 a1 = *(float4*)&As[k][ty*8+4];
            float4 b0 = *(float4*)&Bs[k][tx*8];
            float4 b1 = *(float4*)&Bs[k][tx*8+4];
            ull bp[4] = {pk2(b0.x,b0.y), pk2(b0.z,b0.w), pk2(b1.x,b1.y), pk2(b1.z,b1.w)};
            float av[8] = {a0.x,a0.y,a0.z,a0.w,a1.x,a1.y,a1.z,a1.w};
            #pragma unroll
            for (int i = 0; i < 8; i++) {
                ull aa = pk2(av[i], av[i]);
                #pragma unroll
                for (int j = 0; j < 4; j++)
                    fma2(acc[i][j], aa, bp[j]);
            }
        }
        __syncthreads();
    }
    #pragma unroll
    for (int i = 0; i < 8; i++) {
        float2 p0 = up2(acc[i][0]), p1 = up2(acc[i][1]);
        float2 p2 = up2(acc[i][2]), p3 = up2(acc[i][3]);
        float v[8] = {p0.x,p0.y,p1.x,p1.y,p2.x,p2.y,p3.x,p3.y};
        float mx = -1e30f;
        #pragma unroll
        for (int j = 0; j < 8; j++) { v[j] *= SCALE_; mx = fmaxf(mx, v[j]); }
        #pragma unroll
        for (int off = 16; off >= 1; off >>= 1)
            mx = fmaxf(mx, __shfl_xor_sync(0xffffffffu, mx, off));
        float4 o0, o1;
        o0.x = __expf(v[0]-mx)+EPS_; o0.y = __expf(v[1]-mx)+EPS_;
        o0.z = __expf(v[2]-mx)+EPS_; o0.w = __expf(v[3]-mx)+EPS_;
        o1.x = __expf(v[4]-mx)+EPS_; o1.y = __expf(v[5]-mx)+EPS_;
        o1.z = __expf(v[6]-mx)+EPS_; o1.w = __expf(v[7]-mx)+EPS_;
        size_t m = m0 + ty*8 + i;
        float4* dst = (float4*)(outF + m*R_ + tx*8);
        dst[0] = o0;
        dst[1] = o1;
    }
}

// ---------------- kv partial sums ----------------
__global__ void kvsum_kernel(const float* __restrict__ kf, const float* __restrict__ v,
                             float* __restrict__ kvp, float* __restrict__ ksump) {
    __shared__ float kfs[32*256];
    __shared__ float vs[32*64];
    int bh = blockIdx.x, sp = blockIdx.y;
    int b = bh >> 3, h = bh & 7;
    int t = threadIdx.x, tx = t & 15, ty = t >> 4;
    ull acc[8][4] = {};
    float ks = 0.f;
    int sbase = sp*256;
    for (int s0 = 0; s0 < 256; s0 += 32) {
        #pragma unroll
        for (int j = 0; j < 8; j++) {
            int idx = t + 256*j;
            int si = idx >> 6, c = idx & 63;
            size_t row = (size_t)(b*S_ + sbase + s0 + si)*H_ + h;
            ((float4*)kfs)[idx] = ((const float4*)(kf + row*R_))[c];
        }
        #pragma unroll
        for (int j = 0; j < 2; j++) {
            int idx = t + 256*j;
            int si = idx >> 4, c = idx & 15;
            size_t row = (size_t)(b*S_ + sbase + s0 + si)*H_ + h;
            ((float4*)vs)[idx] = ((const float4*)(v + row*KD_))[c];
        }
        __syncthreads();
        for (int si = 0; si < 32; si++) {
            ks += kfs[si*256 + t];
            float4 v4 = ((float4*)(vs + si*64))[tx];
            ull vd[4] = {pk2(v4.x,v4.x), pk2(v4.y,v4.y), pk2(v4.z,v4.z), pk2(v4.w,v4.w)};
            const float2* arow = (const float2*)(kfs + si*256 + ty*16);
            #pragma unroll
            for (int i2 = 0; i2 < 8; i2++) {
                float2 ap = arow[i2];
                ull aa = pk2(ap.x, ap.y);
                #pragma unroll
                for (int j = 0; j < 4; j++)
                    fma2(acc[i2][j], aa, vd[j]);
            }
        }
        __syncthreads();
    }
    size_t base = ((size_t)bh*NSPLIT + sp)*R_;
    ksump[base + t] = ks;
    #pragma unroll
    for (int i2 = 0; i2 < 8; i2++) {
        float2 c0 = up2(acc[i2][0]), c1 = up2(acc[i2][1]);
        float2 c2 = up2(acc[i2][2]), c3 = up2(acc[i2][3]);
        int r0 = ty*16 + 2*i2;
        *(float4*)(kvp + (base + r0)*KD_ + tx*4)     = make_float4(c0.x, c1.x, c2.x, c3.x);
        *(float4*)(kvp + (base + r0 + 1)*KD_ + tx*4) = make_float4(c0.y, c1.y, c2.y, c3.y);
    }
}

// ---------------- deterministic split reduce ----------------
__global__ void reduce_kernel(const float* __restrict__ kvp, const float* __restrict__ ksump,
                              float* __restrict__ kv, float* __restrict__ ksum) {
    int idx = blockIdx.x*256 + threadIdx.x;
    const int NKV = B_*H_*R_*KD_;
    if (idx < NKV) {
        int bh = idx >> 14;
        int rd = idx & 16383;
        float s = 0.f;
        #pragma unroll
        for (int sp = 0; sp < NSPLIT; sp++)
            s += kvp[((size_t)(bh*NSPLIT + sp) << 14) + rd];
        kv[idx] = s;
    } else {
        int j = idx - NKV;
        if (j < B_*H_*R_) {
            int bh = j >> 8, r = j & 255;
            float s = 0.f;
            #pragma unroll
            for (int sp = 0; sp < NSPLIT; sp++)
                s += ksump[(bh*NSPLIT + sp)*R_ + r];
            ksum[j] = s;
        }
    }
}

// ---------------- attn ----------------
__global__ void attn_kernel(const float* __restrict__ qf, const float* __restrict__ kv,
                            const float* __restrict__ ksum, float* __restrict__ attn) {
    __shared__ float qfs[64*32];
    __shared__ float kvs[32*64];
    __shared__ float kss[256];
    int bh = blockIdx.x, b = bh >> 3, h = bh & 7;
    int s0 = blockIdx.y * 64;
    int t = threadIdx.x, tx = t & 15, ty = t >> 4;
    kss[t] = ksum[bh*R_ + t];
    ull acc[4][2] = {};
    float den[4] = {};
    for (int rb = 0; rb < R_; rb += 32) {
        #pragma unroll
        for (int j = 0; j < 2; j++) {
            int idx = t + 256*j;
            int row = idx >> 3, c = idx & 7;
            size_t g = ((size_t)(b*S_ + s0 + row)*H_ + h)*R_ + rb;
            ((float4*)qfs)[idx] = ((const float4*)(qf + g))[c];
        }
        #pragma unroll
        for (int j = 0; j < 2; j++) {
            int idx = t + 256*j;
            int k = idx >> 4, c = idx & 15;
            ((float4*)kvs)[idx] = ((const float4*)(kv + ((size_t)bh*R_ + rb + k)*KD_))[c];
        }
        __syncthreads();
        #pragma unroll
        for (int k = 0; k < 32; k++) {
            float4 b4 = ((float4*)(kvs + k*64))[tx];
            ull bp0 = pk2(b4.x, b4.y), bp1 = pk2(b4.z, b4.w);
            float ksv = kss[rb + k];
            #pragma unroll
            for (int i = 0; i < 4; i++) {
                float a = qfs[(ty*4+i)*32 + k];
                den[i] += a*ksv;
                ull aa = pk2(a, a);
                fma2(acc[i][0], aa, bp0);
                fma2(acc[i][1], aa, bp1);
            }
        }
        __syncthreads();
    }
    #pragma unroll
    for (int i = 0; i < 4; i++) {
        int s = s0 + ty*4 + i;
        float inv = 1.0f / (den[i] + EPS_);
        float2 c0 = up2(acc[i][0]), c1 = up2(acc[i][1]);
        float4 o = make_float4(c0.x*inv, c0.y*inv, c1.x*inv, c1.y*inv);
        *(float4*)(attn + (size_t)(b*S_ + s)*D_ + h*KD_ + tx*4) = o;
    }
}

// ---------------- launch ----------------
extern "C" void kernel_launch(void* const* d_in, const int* in_sizes, int n_in,
                              void* d_out, int out_size) {
    const float* x  = (const float*)d_in[0];
    const float* Wq = (const float*)d_in[1];
    const float* Wk = (const float*)d_in[2];
    const float* Wv = (const float*)d_in[3];
    const float* rf = (const float*)d_in[4];
    const float* Wo = (const float*)d_in[5];
    const float* bo = (const float*)d_in[6];
    float* out = (float*)d_out;

    float *pq, *pk, *pv, *pqf, *pkf, *pkvp, *pksp, *pkv, *pks, *pattn;
    __nv_bfloat16 *pxh, *pxl, *pah, *pal, *pwh, *pwl;
    cudaGetSymbolAddress((void**)&pq,   g_q);
    cudaGetSymbolAddress((void**)&pk,   g_k);
    cudaGetSymbolAddress((void**)&pv,   g_v);
    cudaGetSymbolAddress((void**)&pqf,  g_qf);
    cudaGetSymbolAddress((void**)&pkf,  g_kf);
    cudaGetSymbolAddress((void**)&pkvp, g_kvp);
    cudaGetSymbolAddress((void**)&pksp, g_ksump);
    cudaGetSymbolAddress((void**)&pkv,  g_kv);
    cudaGetSymbolAddress((void**)&pks,  g_ksum);
    cudaGetSymbolAddress((void**)&pattn,g_attn);
    cudaGetSymbolAddress((void**)&pxh,  g_xh);
    cudaGetSymbolAddress((void**)&pxl,  g_xl);
    cudaGetSymbolAddress((void**)&pah,  g_ah);
    cudaGetSymbolAddress((void**)&pal,  g_al);
    cudaGetSymbolAddress((void**)&pwh,  g_wh);
    cudaGetSymbolAddress((void**)&pwl,  g_wl);

    cudaFuncSetAttribute(mma_gemm, cudaFuncAttributeMaxDynamicSharedMemorySize, MMSM);

    const int WSZ = D_*D_;
    dim3 wgrid(16, 16), wblk(32, 8);
    wsplit_kernel<<<wgrid, wblk>>>(Wq, pwh + 0*WSZ, pwl + 0*WSZ);
    wsplit_kernel<<<wgrid, wblk>>>(Wk, pwh + 1*WSZ, pwl + 1*WSZ);
    wsplit_kernel<<<wgrid, wblk>>>(Wv, pwh + 2*WSZ, pwl + 2*WSZ);
    wsplit_kernel<<<wgrid, wblk>>>(Wo, pwh + 3*WSZ, pwl + 3*WSZ);

    split_kernel<<<M_*D_/4/256, 256>>>((const float4*)x, (uint2*)pxh, (uint2*)pxl);

    dim3 tg(D_/128, M_/128);   // (4, 128)
    mma_gemm<<<tg, 256, MMSM>>>(pxh, pxl, pwh + 0*WSZ, pwl + 0*WSZ, pq, nullptr);
    mma_gemm<<<tg, 256, MMSM>>>(pxh, pxl, pwh + 1*WSZ, pwl + 1*WSZ, pk, nullptr);
    mma_gemm<<<tg, 256, MMSM>>>(pxh, pxl, pwh + 2*WSZ, pwl + 2*WSZ, pv, nullptr);

    feat_kernel<<<ROWS_/64, 256>>>(pq, rf, pqf);
    feat_kernel<<<ROWS_/64, 256>>>(pk, rf, pkf);

    kvsum_kernel<<<dim3(B_*H_, NSPLIT), 256>>>(pkf, pv, pkvp, pksp);
    reduce_kernel<<<(B_*H_*R_*KD_ + B_*H_*R_ + 255)/256, 256>>>(pkvp, pksp, pkv, pks);

    attn_kernel<<<dim3(B_*H_, S_/64), 256>>>(pqf, pkv, pks, pattn);

    split_kernel<<<M_*D_/4/256, 256>>>((const float4*)pattn, (uint2*)pah, (uint2*)pal);
    mma_gemm<<<tg, 256, MMSM>>>(pah, pal, pwh + 3*WSZ, pwl + 3*WSZ, out, bo);
}

// round 8
// speedup vs baseline: 3.4875x; 1.1557x over previous
#include <cuda_runtime.h>
#include <cuda_bf16.h>
#include <cstdint>
#include <math.h>

#define B_   4
#define S_   4096
#define D_   512
#define H_   8
#define KD_  64
#define R_   256
#define M_   (B_*S_)       // 16384 rows of x
#define ROWS_ (M_*H_)      // 131072 (b,s,h) rows
#define EPS_ 1e-3f
#define SCALE_ 0.125f      // 1/sqrt(64)
#define NSPLIT 16

typedef unsigned long long ull;

// ---- packed f32x2 helpers ----
__device__ __forceinline__ ull pk2(float a, float b) {
    ull r; asm("mov.b64 %0, {%1,%2};" : "=l"(r) : "f"(a), "f"(b)); return r;
}
__device__ __forceinline__ void fma2(ull& d, ull a, ull b) {
    asm("fma.rn.f32x2 %0, %1, %2, %0;" : "+l"(d) : "l"(a), "l"(b));
}
__device__ __forceinline__ float2 up2(ull v) {
    float2 f; asm("mov.b64 {%0,%1}, %2;" : "=f"(f.x), "=f"(f.y) : "l"(v)); return f;
}

// ---- mma.sync / ldmatrix / cp.async helpers (baseline sm_80+ PTX) ----
__device__ __forceinline__ uint32_t smem_u32(const void* p) {
    uint32_t a;
    asm("{ .reg .u64 t; cvta.to.shared.u64 t, %1; cvt.u32.u64 %0, t; }" : "=r"(a) : "l"(p));
    return a;
}
__device__ __forceinline__ void ldsm4(uint32_t& r0, uint32_t& r1, uint32_t& r2, uint32_t& r3,
                                      uint32_t addr) {
    asm volatile("ldmatrix.sync.aligned.m8n8.x4.shared.b16 {%0,%1,%2,%3}, [%4];"
                 : "=r"(r0), "=r"(r1), "=r"(r2), "=r"(r3) : "r"(addr));
}
__device__ __forceinline__ void mma16816(float* c, const uint32_t* a, const uint32_t* b) {
    asm volatile("mma.sync.aligned.m16n8k16.row.col.f32.bf16.bf16.f32 "
                 "{%0,%1,%2,%3}, {%4,%5,%6,%7}, {%8,%9}, {%0,%1,%2,%3};"
                 : "+f"(c[0]), "+f"(c[1]), "+f"(c[2]), "+f"(c[3])
                 : "r"(a[0]), "r"(a[1]), "r"(a[2]), "r"(a[3]), "r"(b[0]), "r"(b[1]));
}
__device__ __forceinline__ void cpa16(uint32_t dst, const void* src) {
    asm volatile("cp.async.cg.shared.global [%0], [%1], 16;" :: "r"(dst), "l"(src));
}
#define CPA_COMMIT() asm volatile("cp.async.commit_group;" ::: "memory")
#define CPA_WAIT(n)  asm volatile("cp.async.wait_group %0;" :: "n"(n) : "memory")

// ---------------- scratch ----------------
__device__ float g_v[M_*D_];
__device__ float g_qf[(size_t)ROWS_*R_];
__device__ float g_kf[(size_t)ROWS_*R_];
__device__ float g_kvp[B_*H_*NSPLIT*R_*KD_];
__device__ float g_ksump[B_*H_*NSPLIT*R_];
__device__ float g_kv[B_*H_*R_*KD_];
__device__ float g_ksum[B_*H_*R_];
__device__ float g_attn[M_*D_];
__device__ __nv_bfloat16 g_xh[M_*D_];
__device__ __nv_bfloat16 g_xl[M_*D_];
__device__ __nv_bfloat16 g_ah[M_*D_];
__device__ __nv_bfloat16 g_al[M_*D_];
__device__ __nv_bfloat16 g_qh[M_*D_];   // Q/K outputs as hi/lo (512 = H*KD cols)
__device__ __nv_bfloat16 g_ql[M_*D_];
__device__ __nv_bfloat16 g_kh[M_*D_];
__device__ __nv_bfloat16 g_kl[M_*D_];
__device__ __nv_bfloat16 g_rfh[R_*KD_];
__device__ __nv_bfloat16 g_rfl[R_*KD_];
__device__ __nv_bfloat16 g_wh[4][D_*D_];   // transposed weights hi: [n][k]
__device__ __nv_bfloat16 g_wl[4][D_*D_];   // transposed weights lo

// ---------------- fp32 -> bf16 hi/lo split ----------------
__global__ void split_kernel(const float4* __restrict__ src,
                             uint2* __restrict__ hi, uint2* __restrict__ lo) {
    int i = blockIdx.x*256 + threadIdx.x;
    float4 v = src[i];
    __nv_bfloat16 h0 = __float2bfloat16(v.x), h1 = __float2bfloat16(v.y);
    __nv_bfloat16 h2 = __float2bfloat16(v.z), h3 = __float2bfloat16(v.w);
    __nv_bfloat16 l0 = __float2bfloat16(v.x - __bfloat162float(h0));
    __nv_bfloat16 l1 = __float2bfloat16(v.y - __bfloat162float(h1));
    __nv_bfloat16 l2 = __float2bfloat16(v.z - __bfloat162float(h2));
    __nv_bfloat16 l3 = __float2bfloat16(v.w - __bfloat162float(h3));
    __nv_bfloat162 hp0; hp0.x = h0; hp0.y = h1;
    __nv_bfloat162 hp1; hp1.x = h2; hp1.y = h3;
    __nv_bfloat162 lp0; lp0.x = l0; lp0.y = l1;
    __nv_bfloat162 lp1; lp1.x = l2; lp1.y = l3;
    hi[i] = make_uint2(*(uint32_t*)&hp0, *(uint32_t*)&hp1);
    lo[i] = make_uint2(*(uint32_t*)&lp0, *(uint32_t*)&lp1);
}

// ---------------- W[k][n] -> Wt[n][k] bf16 hi/lo (transpose + split) ----------------
__global__ void wsplit_kernel(const float* __restrict__ W,
                              __nv_bfloat16* __restrict__ Th, __nv_bfloat16* __restrict__ Tl) {
    __shared__ float tile[32][33];
    int n0 = blockIdx.x*32, k0 = blockIdx.y*32;
    int tx = threadIdx.x, ty = threadIdx.y;    // (32, 8)
    #pragma unroll
    for (int j = 0; j < 32; j += 8)
        tile[ty+j][tx] = W[(size_t)(k0+ty+j)*D_ + n0+tx];
    __syncthreads();
    #pragma unroll
    for (int j = 0; j < 32; j += 8) {
        float v = tile[tx][ty+j];
        __nv_bfloat16 h = __float2bfloat16(v);
        __nv_bfloat16 l = __float2bfloat16(v - __bfloat162float(h));
        Th[(size_t)(n0+ty+j)*D_ + k0+tx] = h;
        Tl[(size_t)(n0+ty+j)*D_ + k0+tx] = l;
    }
}

// ---------------- HMMA bf16-split GEMM, double-buffered cp.async pipeline -------------
// OUTMODE 0: fp32 C (+bias).  OUTMODE 1: bf16 hi/lo C (no bias).
#define AST 72
#define TILE_BYTES (128*AST*2)          // 18432 per tile
#define BUF_BYTES  (4*TILE_BYTES)       // 73728: Ah, Al, Bh, Bl
#define MMSM (2*BUF_BYTES)              // 147456
template<int OUTMODE>
__global__ void __launch_bounds__(256) mma_gemm_t(
        const __nv_bfloat16* __restrict__ Ah_g, const __nv_bfloat16* __restrict__ Al_g,
        const __nv_bfloat16* __restrict__ Bh_g, const __nv_bfloat16* __restrict__ Bl_g,
        float* __restrict__ C, const float* __restrict__ bias,
        __nv_bfloat16* __restrict__ Ch, __nv_bfloat16* __restrict__ Cl) {
    extern __shared__ __nv_bfloat16 sm[];
    uint32_t sbase = smem_u32(sm);
    int t = threadIdx.x, lane = t & 31, w = t >> 5;
    int wm = w & 3, wn = w >> 2;
    int n0 = blockIdx.x * 128;
    size_t m0 = (size_t)blockIdx.y * 128;

    float acc[2][8][4] = {};

    int a_row = wm*32 + (lane & 15);
    int a_col8 = (lane >> 4) * 8;
    int b_row = wn*64 + ((lane >> 4) & 1)*8 + (lane & 7);
    int b_col8 = ((lane >> 3) & 1) * 8;

    int srow[4], sc8[4];
    #pragma unroll
    for (int j = 0; j < 4; j++) { int idx = t + j*256; srow[j] = idx >> 3; sc8[j] = idx & 7; }

    {
        uint32_t bb = sbase;
        #pragma unroll
        for (int j = 0; j < 4; j++) {
            uint32_t off = (uint32_t)(srow[j]*AST + sc8[j]*8)*2;
            cpa16(bb + 0*TILE_BYTES + off, Ah_g + (m0+srow[j])*D_ + 0 + sc8[j]*8);
            cpa16(bb + 1*TILE_BYTES + off, Al_g + (m0+srow[j])*D_ + 0 + sc8[j]*8);
            cpa16(bb + 2*TILE_BYTES + off, Bh_g + (size_t)(n0+srow[j])*D_ + 0 + sc8[j]*8);
            cpa16(bb + 3*TILE_BYTES + off, Bl_g + (size_t)(n0+srow[j])*D_ + 0 + sc8[j]*8);
        }
        CPA_COMMIT();
    }

    for (int c = 0; c < 8; c++) {
        int buf = c & 1;
        if (c < 7) {
            int kb = (c+1)*64;
            uint32_t bb = sbase + (buf^1)*BUF_BYTES;
            #pragma unroll
            for (int j = 0; j < 4; j++) {
                uint32_t off = (uint32_t)(srow[j]*AST + sc8[j]*8)*2;
                cpa16(bb + 0*TILE_BYTES + off, Ah_g + (m0+srow[j])*D_ + kb + sc8[j]*8);
                cpa16(bb + 1*TILE_BYTES + off, Al_g + (m0+srow[j])*D_ + kb + sc8[j]*8);
                cpa16(bb + 2*TILE_BYTES + off, Bh_g + (size_t)(n0+srow[j])*D_ + kb + sc8[j]*8);
                cpa16(bb + 3*TILE_BYTES + off, Bl_g + (size_t)(n0+srow[j])*D_ + kb + sc8[j]*8);
            }
            CPA_COMMIT();
            CPA_WAIT(1);
        } else {
            CPA_WAIT(0);
        }
        __syncthreads();

        uint32_t bb = sbase + buf*BUF_BYTES;
        uint32_t sAh_b = bb, sAl_b = bb + TILE_BYTES;
        uint32_t sBh_b = bb + 2*TILE_BYTES, sBl_b = bb + 3*TILE_BYTES;

        #pragma unroll
        for (int k16 = 0; k16 < 4; k16++) {
            int ak = k16*16 + a_col8;
            int bk = k16*16 + b_col8;
            #pragma unroll
            for (int pass = 0; pass < 3; pass++) {
                uint32_t aBase = (pass == 2) ? sAl_b : sAh_b;
                uint32_t bBase = (pass == 1) ? sBl_b : sBh_b;
                uint32_t aF[2][4];
                #pragma unroll
                for (int mt = 0; mt < 2; mt++) {
                    uint32_t addr = aBase + (uint32_t)((a_row + mt*16)*AST + ak)*2;
                    ldsm4(aF[mt][0], aF[mt][1], aF[mt][2], aF[mt][3], addr);
                }
                uint32_t bF[8][2];
                #pragma unroll
                for (int p = 0; p < 4; p++) {
                    uint32_t addr = bBase + (uint32_t)((b_row + p*16)*AST + bk)*2;
                    uint32_t r0, r1, r2, r3;
                    ldsm4(r0, r1, r2, r3, addr);
                    bF[2*p][0]   = r0; bF[2*p][1]   = r1;
                    bF[2*p+1][0] = r2; bF[2*p+1][1] = r3;
                }
                #pragma unroll
                for (int mt = 0; mt < 2; mt++)
                    #pragma unroll
                    for (int nt = 0; nt < 8; nt++)
                        mma16816(acc[mt][nt], aF[mt], bF[nt]);
            }
        }
        __syncthreads();
    }

    int g = lane >> 2;
    int cl = (lane & 3) * 2;
    #pragma unroll
    for (int mt = 0; mt < 2; mt++) {
        #pragma unroll
        for (int nt = 0; nt < 8; nt++) {
            int col = n0 + wn*64 + nt*8 + cl;
            size_t r0 = m0 + wm*32 + mt*16 + g;
            if (OUTMODE == 0) {
                float bx = 0.f, by = 0.f;
                if (bias) { bx = bias[col]; by = bias[col+1]; }
                *(float2*)(C + r0*D_ + col)       = make_float2(acc[mt][nt][0] + bx, acc[mt][nt][1] + by);
                *(float2*)(C + (r0 + 8)*D_ + col) = make_float2(acc[mt][nt][2] + bx, acc[mt][nt][3] + by);
            } else {
                #pragma unroll
                for (int half = 0; half < 2; half++) {
                    float vx = acc[mt][nt][2*half], vy = acc[mt][nt][2*half+1];
                    __nv_bfloat16 hx = __float2bfloat16(vx);
                    __nv_bfloat16 hy = __float2bfloat16(vy);
                    __nv_bfloat16 lx = __float2bfloat16(vx - __bfloat162float(hx));
                    __nv_bfloat16 ly = __float2bfloat16(vy - __bfloat162float(hy));
                    __nv_bfloat162 hp; hp.x = hx; hp.y = hy;
                    __nv_bfloat162 lp; lp.x = lx; lp.y = ly;
                    size_t rr = r0 + half*8;
                    *(uint32_t*)(Ch + rr*D_ + col) = *(uint32_t*)&hp;
                    *(uint32_t*)(Cl + rr*D_ + col) = *(uint32_t*)&lp;
                }
            }
        }
    }
}

// ---------------- feat via HMMA: outF[m,r] = exp(SCALE*(A[m,:].rf[r,:]) - rowmax) + EPS
// A = q/k hi-lo bf16 viewed as [ROWS_][64]; rf hi/lo [256][64].
// Block: 128 rows x 256 cols, K=64 (single chunk). 8 warps, warp = 16 rows x all 256 cols.
#define FSM_A (128*AST*2)               // 18432 per A tile
#define FSM_B (256*AST*2)               // 36864 per B tile
#define FSM_TOT (2*FSM_A + 2*FSM_B)     // 110592
__global__ void __launch_bounds__(256) feat_mma(
        const __nv_bfloat16* __restrict__ Ah_g, const __nv_bfloat16* __restrict__ Al_g,
        const __nv_bfloat16* __restrict__ rfh, const __nv_bfloat16* __restrict__ rfl,
        float* __restrict__ outF) {
    extern __shared__ __nv_bfloat16 sm[];
    uint32_t sbase = smem_u32(sm);
    uint32_t sAh_b = sbase, sAl_b = sbase + FSM_A;
    uint32_t sBh_b = sbase + 2*FSM_A, sBl_b = sbase + 2*FSM_A + FSM_B;
    int t = threadIdx.x, lane = t & 31, w = t >> 5;
    size_t m0 = (size_t)blockIdx.x * 128;

    // stage A hi/lo (128x64) + rf hi/lo (256x64)
    #pragma unroll
    for (int j = 0; j < 4; j++) {
        int idx = t + j*256;               // 0..1023
        int row = idx >> 3, c8 = idx & 7;
        uint32_t off = (uint32_t)(row*AST + c8*8)*2;
        cpa16(sAh_b + off, Ah_g + (m0+row)*KD_ + c8*8);
        cpa16(sAl_b + off, Al_g + (m0+row)*KD_ + c8*8);
    }
    #pragma unroll
    for (int j = 0; j < 8; j++) {
        int idx = t + j*256;               // 0..2047
        int row = idx >> 3, c8 = idx & 7;
        uint32_t off = (uint32_t)(row*AST + c8*8)*2;
        cpa16(sBh_b + off, rfh + row*KD_ + c8*8);
        cpa16(sBl_b + off, rfl + row*KD_ + c8*8);
    }
    CPA_COMMIT();
    CPA_WAIT(0);
    __syncthreads();

    float acc[32][4] = {};
    int a_row = w*16 + (lane & 15);
    int a_col8 = (lane >> 4) * 8;
    int b_row = ((lane >> 4) & 1)*8 + (lane & 7);
    int b_col8 = ((lane >> 3) & 1) * 8;

    #pragma unroll
    for (int k16 = 0; k16 < 4; k16++) {
        #pragma unroll
        for (int pass = 0; pass < 3; pass++) {
            uint32_t aBase = (pass == 2) ? sAl_b : sAh_b;
            uint32_t bBase = (pass == 1) ? sBl_b : sBh_b;
            uint32_t aF[4];
            ldsm4(aF[0], aF[1], aF[2], aF[3],
                  aBase + (uint32_t)(a_row*AST + k16*16 + a_col8)*2);
            #pragma unroll
            for (int p = 0; p < 16; p++) {
                uint32_t r0, r1, r2, r3;
                ldsm4(r0, r1, r2, r3,
                      bBase + (uint32_t)((p*16 + b_row)*AST + k16*16 + b_col8)*2);
                uint32_t bf0[2] = {r0, r1}, bf1[2] = {r2, r3};
                mma16816(acc[2*p],   aF, bf0);
                mma16816(acc[2*p+1], aF, bf1);
            }
        }
    }

    // epilogue: scale, rowmax (thread-reduce + quad shfl), exp, store
    int g = lane >> 2;
    float mx0 = -1e30f, mx1 = -1e30f;
    #pragma unroll
    for (int nt = 0; nt < 32; nt++) {
        acc[nt][0] *= SCALE_; acc[nt][1] *= SCALE_;
        acc[nt][2] *= SCALE_; acc[nt][3] *= SCALE_;
        mx0 = fmaxf(mx0, fmaxf(acc[nt][0], acc[nt][1]));
        mx1 = fmaxf(mx1, fmaxf(acc[nt][2], acc[nt][3]));
    }
    mx0 = fmaxf(mx0, __shfl_xor_sync(0xffffffffu, mx0, 1));
    mx0 = fmaxf(mx0, __shfl_xor_sync(0xffffffffu, mx0, 2));
    mx1 = fmaxf(mx1, __shfl_xor_sync(0xffffffffu, mx1, 1));
    mx1 = fmaxf(mx1, __shfl_xor_sync(0xffffffffu, mx1, 2));

    size_t row0 = m0 + w*16 + g;
    int cl = (lane & 3) * 2;
    #pragma unroll
    for (int nt = 0; nt < 32; nt++) {
        int col = nt*8 + cl;
        *(float2*)(outF + row0*R_ + col) =
            make_float2(__expf(acc[nt][0]-mx0)+EPS_, __expf(acc[nt][1]-mx0)+EPS_);
        *(float2*)(outF + (row0+8)*R_ + col) =
            make_float2(__expf(acc[nt][2]-mx1)+EPS_, __expf(acc[nt][3]-mx1)+EPS_);
    }
}

// ---------------- kv partial sums ----------------
__global__ void kvsum_kernel(const float* __restrict__ kf, const float* __restrict__ v,
                             float* __restrict__ kvp, float* __restrict__ ksump) {
    __shared__ float kfs[32*256];
    __shared__ float vs[32*64];
    int bh = blockIdx.x, sp = blockIdx.y;
    int b = bh >> 3, h = bh & 7;
    int t = threadIdx.x, tx = t & 15, ty = t >> 4;
    ull acc[8][4] = {};
    float ks = 0.f;
    int sbase = sp*256;
    for (int s0 = 0; s0 < 256; s0 += 32) {
        #pragma unroll
        for (int j = 0; j < 8; j++) {
            int idx = t + 256*j;
            int si = idx >> 6, c = idx & 63;
            size_t row = (size_t)(b*S_ + sbase + s0 + si)*H_ + h;
            ((float4*)kfs)[idx] = ((const float4*)(kf + row*R_))[c];
        }
        #pragma unroll
        for (int j = 0; j < 2; j++) {
            int idx = t + 256*j;
            int si = idx >> 4, c = idx & 15;
            size_t row = (size_t)(b*S_ + sbase + s0 + si)*H_ + h;
            ((float4*)vs)[idx] = ((const float4*)(v + row*KD_))[c];
        }
        __syncthreads();
        for (int si = 0; si < 32; si++) {
            ks += kfs[si*256 + t];
            float4 v4 = ((float4*)(vs + si*64))[tx];
            ull vd[4] = {pk2(v4.x,v4.x), pk2(v4.y,v4.y), pk2(v4.z,v4.z), pk2(v4.w,v4.w)};
            const float2* arow = (const float2*)(kfs + si*256 + ty*16);
            #pragma unroll
            for (int i2 = 0; i2 < 8; i2++) {
                float2 ap = arow[i2];
                ull aa = pk2(ap.x, ap.y);
                #pragma unroll
                for (int j = 0; j < 4; j++)
                    fma2(acc[i2][j], aa, vd[j]);
            }
        }
        __syncthreads();
    }
    size_t base = ((size_t)bh*NSPLIT + sp)*R_;
    ksump[base + t] = ks;
    #pragma unroll
    for (int i2 = 0; i2 < 8; i2++) {
        float2 c0 = up2(acc[i2][0]), c1 = up2(acc[i2][1]);
        float2 c2 = up2(acc[i2][2]), c3 = up2(acc[i2][3]);
        int r0 = ty*16 + 2*i2;
        *(float4*)(kvp + (base + r0)*KD_ + tx*4)     = make_float4(c0.x, c1.x, c2.x, c3.x);
        *(float4*)(kvp + (base + r0 + 1)*KD_ + tx*4) = make_float4(c0.y, c1.y, c2.y, c3.y);
    }
}

// ---------------- deterministic split reduce ----------------
__global__ void reduce_kernel(const float* __restrict__ kvp, const float* __restrict__ ksump,
                              float* __restrict__ kv, float* __restrict__ ksum) {
    int idx = blockIdx.x*256 + threadIdx.x;
    const int NKV = B_*H_*R_*KD_;
    if (idx < NKV) {
        int bh = idx >> 14;
        int rd = idx & 16383;
        float s = 0.f;
        #pragma unroll
        for (int sp = 0; sp < NSPLIT; sp++)
            s += kvp[((size_t)(bh*NSPLIT + sp) << 14) + rd];
        kv[idx] = s;
    } else {
        int j = idx - NKV;
        if (j < B_*H_*R_) {
            int bh = j >> 8, r = j & 255;
            float s = 0.f;
            #pragma unroll
            for (int sp = 0; sp < NSPLIT; sp++)
                s += ksump[(bh*NSPLIT + sp)*R_ + r];
            ksum[j] = s;
        }
    }
}

// ---------------- attn ----------------
__global__ void attn_kernel(const float* __restrict__ qf, const float* __restrict__ kv,
                            const float* __restrict__ ksum, float* __restrict__ attn) {
    __shared__ float qfs[64*32];
    __shared__ float kvs[32*64];
    __shared__ float kss[256];
    int bh = blockIdx.x, b = bh >> 3, h = bh & 7;
    int s0 = blockIdx.y * 64;
    int t = threadIdx.x, tx = t & 15, ty = t >> 4;
    kss[t] = ksum[bh*R_ + t];
    ull acc[4][2] = {};
    float den[4] = {};
    for (int rb = 0; rb < R_; rb += 32) {
        #pragma unroll
        for (int j = 0; j < 2; j++) {
            int idx = t + 256*j;
            int row = idx >> 3, c = idx & 7;
            size_t g = ((size_t)(b*S_ + s0 + row)*H_ + h)*R_ + rb;
            ((float4*)qfs)[idx] = ((const float4*)(qf + g))[c];
        }
        #pragma unroll
        for (int j = 0; j < 2; j++) {
            int idx = t + 256*j;
            int k = idx >> 4, c = idx & 15;
            ((float4*)kvs)[idx] = ((const float4*)(kv + ((size_t)bh*R_ + rb + k)*KD_))[c];
        }
        __syncthreads();
        #pragma unroll
        for (int k = 0; k < 32; k++) {
            float4 b4 = ((float4*)(kvs + k*64))[tx];
            ull bp0 = pk2(b4.x, b4.y), bp1 = pk2(b4.z, b4.w);
            float ksv = kss[rb + k];
            #pragma unroll
            for (int i = 0; i < 4; i++) {
                float a = qfs[(ty*4+i)*32 + k];
                den[i] += a*ksv;
                ull aa = pk2(a, a);
                fma2(acc[i][0], aa, bp0);
                fma2(acc[i][1], aa, bp1);
            }
        }
        __syncthreads();
    }
    #pragma unroll
    for (int i = 0; i < 4; i++) {
        int s = s0 + ty*4 + i;
        float inv = 1.0f / (den[i] + EPS_);
        float2 c0 = up2(acc[i][0]), c1 = up2(acc[i][1]);
        float4 o = make_float4(c0.x*inv, c0.y*inv, c1.x*inv, c1.y*inv);
        *(float4*)(attn + (size_t)(b*S_ + s)*D_ + h*KD_ + tx*4) = o;
    }
}

// ---------------- launch ----------------
extern "C" void kernel_launch(void* const* d_in, const int* in_sizes, int n_in,
                              void* d_out, int out_size) {
    const float* x  = (const float*)d_in[0];
    const float* Wq = (const float*)d_in[1];
    const float* Wk = (const float*)d_in[2];
    const float* Wv = (const float*)d_in[3];
    const float* rf = (const float*)d_in[4];
    const float* Wo = (const float*)d_in[5];
    const float* bo = (const float*)d_in[6];
    float* out = (float*)d_out;

    float *pv, *pqf, *pkf, *pkvp, *pksp, *pkv, *pks, *pattn;
    __nv_bfloat16 *pxh, *pxl, *pah, *pal, *pqh, *pql, *pkh, *pkl, *prfh, *prfl, *pwh, *pwl;
    cudaGetSymbolAddress((void**)&pv,   g_v);
    cudaGetSymbolAddress((void**)&pqf,  g_qf);
    cudaGetSymbolAddress((void**)&pkf,  g_kf);
    cudaGetSymbolAddress((void**)&pkvp, g_kvp);
    cudaGetSymbolAddress((void**)&pksp, g_ksump);
    cudaGetSymbolAddress((void**)&pkv,  g_kv);
    cudaGetSymbolAddress((void**)&pks,  g_ksum);
    cudaGetSymbolAddress((void**)&pattn,g_attn);
    cudaGetSymbolAddress((void**)&pxh,  g_xh);
    cudaGetSymbolAddress((void**)&pxl,  g_xl);
    cudaGetSymbolAddress((void**)&pah,  g_ah);
    cudaGetSymbolAddress((void**)&pal,  g_al);
    cudaGetSymbolAddress((void**)&pqh,  g_qh);
    cudaGetSymbolAddress((void**)&pql,  g_ql);
    cudaGetSymbolAddress((void**)&pkh,  g_kh);
    cudaGetSymbolAddress((void**)&pkl,  g_kl);
    cudaGetSymbolAddress((void**)&prfh, g_rfh);
    cudaGetSymbolAddress((void**)&prfl, g_rfl);
    cudaGetSymbolAddress((void**)&pwh,  g_wh);
    cudaGetSymbolAddress((void**)&pwl,  g_wl);

    cudaFuncSetAttribute(mma_gemm_t<0>, cudaFuncAttributeMaxDynamicSharedMemorySize, MMSM);
    cudaFuncSetAttribute(mma_gemm_t<1>, cudaFuncAttributeMaxDynamicSharedMemorySize, MMSM);
    cudaFuncSetAttribute(feat_mma, cudaFuncAttributeMaxDynamicSharedMemorySize, FSM_TOT);

    const int WSZ = D_*D_;
    dim3 wgrid(16, 16), wblk(32, 8);
    wsplit_kernel<<<wgrid, wblk>>>(Wq, pwh + 0*WSZ, pwl + 0*WSZ);
    wsplit_kernel<<<wgrid, wblk>>>(Wk, pwh + 1*WSZ, pwl + 1*WSZ);
    wsplit_kernel<<<wgrid, wblk>>>(Wv, pwh + 2*WSZ, pwl + 2*WSZ);
    wsplit_kernel<<<wgrid, wblk>>>(Wo, pwh + 3*WSZ, pwl + 3*WSZ);

    split_kernel<<<M_*D_/4/256, 256>>>((const float4*)x, (uint2*)pxh, (uint2*)pxl);
    split_kernel<<<R_*KD_/4/256, 256>>>((const float4*)rf, (uint2*)prfh, (uint2*)prfl);

    dim3 tg(D_/128, M_/128);   // (4, 128)
    mma_gemm_t<1><<<tg, 256, MMSM>>>(pxh, pxl, pwh + 0*WSZ, pwl + 0*WSZ, nullptr, nullptr, pqh, pql);
    mma_gemm_t<1><<<tg, 256, MMSM>>>(pxh, pxl, pwh + 1*WSZ, pwl + 1*WSZ, nullptr, nullptr, pkh, pkl);
    mma_gemm_t<0><<<tg, 256, MMSM>>>(pxh, pxl, pwh + 2*WSZ, pwl + 2*WSZ, pv, nullptr, nullptr, nullptr);

    feat_mma<<<ROWS_/128, 256, FSM_TOT>>>(pqh, pql, prfh, prfl, pqf);
    feat_mma<<<ROWS_/128, 256, FSM_TOT>>>(pkh, pkl, prfh, prfl, pkf);

    kvsum_kernel<<<dim3(B_*H_, NSPLIT), 256>>>(pkf, pv, pkvp, pksp);
    reduce_kernel<<<(B_*H_*R_*KD_ + B_*H_*R_ + 255)/256, 256>>>(pkvp, pksp, pkv, pks);

    attn_kernel<<<dim3(B_*H_, S_/64), 256>>>(pqf, pkv, pks, pattn);

    split_kernel<<<M_*D_/4/256, 256>>>((const float4*)pattn, (uint2*)pah, (uint2*)pal);
    mma_gemm_t<0><<<tg, 256, MMSM>>>(pah, pal, pwh + 3*WSZ, pwl + 3*WSZ, out, bo, nullptr, nullptr);
}

// round 9
// speedup vs baseline: 3.6022x; 1.0329x over previous
#include <cuda_runtime.h>
#include <cuda_bf16.h>
#include <cstdint>
#include <math.h>

#define B_   4
#define S_   4096
#define D_   512
#define H_   8
#define KD_  64
#define R_   256
#define M_   (B_*S_)
#define ROWS_ (M_*H_)
#define EPS_ 1e-3f
#define SCALE_ 0.125f
#define NSPLIT 16

typedef unsigned long long ull;

// ---- packed f32x2 helpers ----
__device__ __forceinline__ ull pk2(float a, float b) {
    ull r; asm("mov.b64 %0, {%1,%2};" : "=l"(r) : "f"(a), "f"(b)); return r;
}
__device__ __forceinline__ void fma2(ull& d, ull a, ull b) {
    asm("fma.rn.f32x2 %0, %1, %2, %0;" : "+l"(d) : "l"(a), "l"(b));
}
__device__ __forceinline__ float2 up2(ull v) {
    float2 f; asm("mov.b64 {%0,%1}, %2;" : "=f"(f.x), "=f"(f.y) : "l"(v)); return f;
}

// ---- mma.sync / ldmatrix / cp.async helpers ----
__device__ __forceinline__ uint32_t smem_u32(const void* p) {
    uint32_t a;
    asm("{ .reg .u64 t; cvta.to.shared.u64 t, %1; cvt.u32.u64 %0, t; }" : "=r"(a) : "l"(p));
    return a;
}
__device__ __forceinline__ void ldsm4(uint32_t& r0, uint32_t& r1, uint32_t& r2, uint32_t& r3,
                                      uint32_t addr) {
    asm volatile("ldmatrix.sync.aligned.m8n8.x4.shared.b16 {%0,%1,%2,%3}, [%4];"
                 : "=r"(r0), "=r"(r1), "=r"(r2), "=r"(r3) : "r"(addr));
}
__device__ __forceinline__ void mma16816(float* c, const uint32_t* a, const uint32_t* b) {
    asm volatile("mma.sync.aligned.m16n8k16.row.col.f32.bf16.bf16.f32 "
                 "{%0,%1,%2,%3}, {%4,%5,%6,%7}, {%8,%9}, {%0,%1,%2,%3};"
                 : "+f"(c[0]), "+f"(c[1]), "+f"(c[2]), "+f"(c[3])
                 : "r"(a[0]), "r"(a[1]), "r"(a[2]), "r"(a[3]), "r"(b[0]), "r"(b[1]));
}
__device__ __forceinline__ void cpa16(uint32_t dst, const void* src) {
    asm volatile("cp.async.cg.shared.global [%0], [%1], 16;" :: "r"(dst), "l"(src));
}
#define CPA_COMMIT() asm volatile("cp.async.commit_group;" ::: "memory")
#define CPA_WAIT(n)  asm volatile("cp.async.wait_group %0;" :: "n"(n) : "memory")

__device__ __forceinline__ void split_bf16(float v, __nv_bfloat16& h, __nv_bfloat16& l) {
    h = __float2bfloat16(v);
    l = __float2bfloat16(v - __bfloat162float(h));
}

// ---------------- scratch ----------------
__device__ float g_v[M_*D_];
__device__ float g_kf[(size_t)ROWS_*R_];
__device__ float g_kvp[B_*H_*NSPLIT*R_*KD_];
__device__ float g_ksump[B_*H_*NSPLIT*R_];
__device__ __nv_bfloat16 g_qfh[(size_t)ROWS_*R_];
__device__ __nv_bfloat16 g_qfl[(size_t)ROWS_*R_];
__device__ __nv_bfloat16 g_kvth[B_*H_*80*R_];
__device__ __nv_bfloat16 g_kvtl[B_*H_*80*R_];
__device__ __nv_bfloat16 g_xh[M_*D_];
__device__ __nv_bfloat16 g_xl[M_*D_];
__device__ __nv_bfloat16 g_ah[M_*D_];
__device__ __nv_bfloat16 g_al[M_*D_];
__device__ __nv_bfloat16 g_qh[M_*D_];
__device__ __nv_bfloat16 g_ql[M_*D_];
__device__ __nv_bfloat16 g_kh[M_*D_];
__device__ __nv_bfloat16 g_kl[M_*D_];
__device__ __nv_bfloat16 g_rfh[R_*KD_];
__device__ __nv_bfloat16 g_rfl[R_*KD_];
__device__ __nv_bfloat16 g_wh[4][D_*D_];
__device__ __nv_bfloat16 g_wl[4][D_*D_];

// ---------------- fp32 -> bf16 hi/lo split ----------------
__global__ void split_kernel(const float4* __restrict__ src,
                             uint2* __restrict__ hi, uint2* __restrict__ lo) {
    int i = blockIdx.x*256 + threadIdx.x;
    float4 v = src[i];
    __nv_bfloat16 h0,h1,h2,h3,l0,l1,l2,l3;
    split_bf16(v.x,h0,l0); split_bf16(v.y,h1,l1);
    split_bf16(v.z,h2,l2); split_bf16(v.w,h3,l3);
    __nv_bfloat162 hp0; hp0.x=h0; hp0.y=h1;
    __nv_bfloat162 hp1; hp1.x=h2; hp1.y=h3;
    __nv_bfloat162 lp0; lp0.x=l0; lp0.y=l1;
    __nv_bfloat162 lp1; lp1.x=l2; lp1.y=l3;
    hi[i] = make_uint2(*(uint32_t*)&hp0, *(uint32_t*)&hp1);
    lo[i] = make_uint2(*(uint32_t*)&lp0, *(uint32_t*)&lp1);
}

// ---------------- all 4 weights: W[k][n] -> Wt[n][k] bf16 hi/lo ----------------
__global__ void wsplit_all(const float* __restrict__ W0, const float* __restrict__ W1,
                           const float* __restrict__ W2, const float* __restrict__ W3,
                           __nv_bfloat16* __restrict__ Th, __nv_bfloat16* __restrict__ Tl) {
    __shared__ float tile[32][33];
    int z = blockIdx.z;
    const float* W = (z == 0) ? W0 : (z == 1) ? W1 : (z == 2) ? W2 : W3;
    __nv_bfloat16* th = Th + (size_t)z*D_*D_;
    __nv_bfloat16* tl = Tl + (size_t)z*D_*D_;
    int n0 = blockIdx.x*32, k0 = blockIdx.y*32;
    int tx = threadIdx.x, ty = threadIdx.y;
    #pragma unroll
    for (int j = 0; j < 32; j += 8)
        tile[ty+j][tx] = W[(size_t)(k0+ty+j)*D_ + n0+tx];
    __syncthreads();
    #pragma unroll
    for (int j = 0; j < 32; j += 8) {
        float v = tile[tx][ty+j];
        __nv_bfloat16 h, l; split_bf16(v, h, l);
        th[(size_t)(n0+ty+j)*D_ + k0+tx] = h;
        tl[(size_t)(n0+ty+j)*D_ + k0+tx] = l;
    }
}

// ---------------- HMMA bf16-split GEMM, double-buffered -------------
#define AST 72
#define TILE_BYTES (128*AST*2)
#define BUF_BYTES  (4*TILE_BYTES)
#define MMSM (2*BUF_BYTES)
template<int OUTMODE>
__global__ void __launch_bounds__(256) mma_gemm_t(
        const __nv_bfloat16* __restrict__ Ah_g, const __nv_bfloat16* __restrict__ Al_g,
        const __nv_bfloat16* __restrict__ Bh_g, const __nv_bfloat16* __restrict__ Bl_g,
        float* __restrict__ C, const float* __restrict__ bias,
        __nv_bfloat16* __restrict__ Ch, __nv_bfloat16* __restrict__ Cl) {
    extern __shared__ __nv_bfloat16 sm[];
    uint32_t sbase = smem_u32(sm);
    int t = threadIdx.x, lane = t & 31, w = t >> 5;
    int wm = w & 3, wn = w >> 2;
    int n0 = blockIdx.x * 128;
    size_t m0 = (size_t)blockIdx.y * 128;

    float acc[2][8][4] = {};

    int a_row = wm*32 + (lane & 15);
    int a_col8 = (lane >> 4) * 8;
    int b_row = wn*64 + ((lane >> 4) & 1)*8 + (lane & 7);
    int b_col8 = ((lane >> 3) & 1) * 8;

    int srow[4], sc8[4];
    #pragma unroll
    for (int j = 0; j < 4; j++) { int idx = t + j*256; srow[j] = idx >> 3; sc8[j] = idx & 7; }

    {
        uint32_t bb = sbase;
        #pragma unroll
        for (int j = 0; j < 4; j++) {
            uint32_t off = (uint32_t)(srow[j]*AST + sc8[j]*8)*2;
            cpa16(bb + 0*TILE_BYTES + off, Ah_g + (m0+srow[j])*D_ + sc8[j]*8);
            cpa16(bb + 1*TILE_BYTES + off, Al_g + (m0+srow[j])*D_ + sc8[j]*8);
            cpa16(bb + 2*TILE_BYTES + off, Bh_g + (size_t)(n0+srow[j])*D_ + sc8[j]*8);
            cpa16(bb + 3*TILE_BYTES + off, Bl_g + (size_t)(n0+srow[j])*D_ + sc8[j]*8);
        }
        CPA_COMMIT();
    }

    for (int c = 0; c < 8; c++) {
        int buf = c & 1;
        if (c < 7) {
            int kb = (c+1)*64;
            uint32_t bb = sbase + (buf^1)*BUF_BYTES;
            #pragma unroll
            for (int j = 0; j < 4; j++) {
                uint32_t off = (uint32_t)(srow[j]*AST + sc8[j]*8)*2;
                cpa16(bb + 0*TILE_BYTES + off, Ah_g + (m0+srow[j])*D_ + kb + sc8[j]*8);
                cpa16(bb + 1*TILE_BYTES + off, Al_g + (m0+srow[j])*D_ + kb + sc8[j]*8);
                cpa16(bb + 2*TILE_BYTES + off, Bh_g + (size_t)(n0+srow[j])*D_ + kb + sc8[j]*8);
                cpa16(bb + 3*TILE_BYTES + off, Bl_g + (size_t)(n0+srow[j])*D_ + kb + sc8[j]*8);
            }
            CPA_COMMIT();
            CPA_WAIT(1);
        } else {
            CPA_WAIT(0);
        }
        __syncthreads();

        uint32_t bb = sbase + buf*BUF_BYTES;
        uint32_t sAh_b = bb, sAl_b = bb + TILE_BYTES;
        uint32_t sBh_b = bb + 2*TILE_BYTES, sBl_b = bb + 3*TILE_BYTES;

        #pragma unroll
        for (int k16 = 0; k16 < 4; k16++) {
            int ak = k16*16 + a_col8;
            int bk = k16*16 + b_col8;
            #pragma unroll
            for (int pass = 0; pass < 3; pass++) {
                uint32_t aBase = (pass == 2) ? sAl_b : sAh_b;
                uint32_t bBase = (pass == 1) ? sBl_b : sBh_b;
                uint32_t aF[2][4];
                #pragma unroll
                for (int mt = 0; mt < 2; mt++) {
                    uint32_t addr = aBase + (uint32_t)((a_row + mt*16)*AST + ak)*2;
                    ldsm4(aF[mt][0], aF[mt][1], aF[mt][2], aF[mt][3], addr);
                }
                uint32_t bF[8][2];
                #pragma unroll
                for (int p = 0; p < 4; p++) {
                    uint32_t addr = bBase + (uint32_t)((b_row + p*16)*AST + bk)*2;
                    uint32_t r0, r1, r2, r3;
                    ldsm4(r0, r1, r2, r3, addr);
                    bF[2*p][0]   = r0; bF[2*p][1]   = r1;
                    bF[2*p+1][0] = r2; bF[2*p+1][1] = r3;
                }
                #pragma unroll
                for (int mt = 0; mt < 2; mt++)
                    #pragma unroll
                    for (int nt = 0; nt < 8; nt++)
                        mma16816(acc[mt][nt], aF[mt], bF[nt]);
            }
        }
        __syncthreads();
    }

    int g = lane >> 2;
    int cl = (lane & 3) * 2;
    #pragma unroll
    for (int mt = 0; mt < 2; mt++) {
        #pragma unroll
        for (int nt = 0; nt < 8; nt++) {
            int col = n0 + wn*64 + nt*8 + cl;
            size_t r0 = m0 + wm*32 + mt*16 + g;
            if (OUTMODE == 0) {
                float bx = 0.f, by = 0.f;
                if (bias) { bx = bias[col]; by = bias[col+1]; }
                *(float2*)(C + r0*D_ + col)       = make_float2(acc[mt][nt][0] + bx, acc[mt][nt][1] + by);
                *(float2*)(C + (r0 + 8)*D_ + col) = make_float2(acc[mt][nt][2] + bx, acc[mt][nt][3] + by);
            } else {
                #pragma unroll
                for (int half = 0; half < 2; half++) {
                    __nv_bfloat16 hx, lx, hy, ly;
                    split_bf16(acc[mt][nt][2*half],   hx, lx);
                    split_bf16(acc[mt][nt][2*half+1], hy, ly);
                    __nv_bfloat162 hp; hp.x = hx; hp.y = hy;
                    __nv_bfloat162 lp; lp.x = lx; lp.y = ly;
                    size_t rr = r0 + half*8;
                    *(uint32_t*)(Ch + rr*D_ + col) = *(uint32_t*)&hp;
                    *(uint32_t*)(Cl + rr*D_ + col) = *(uint32_t*)&lp;
                }
            }
        }
    }
}

// ---------------- feat via HMMA; OUTMODE 0 = fp32, 1 = bf16 hi/lo ----------------
#define FSM_A (128*AST*2)
#define FSM_B (256*AST*2)
#define FSM_TOT (2*FSM_A + 2*FSM_B)
template<int OUTMODE>
__global__ void __launch_bounds__(256) feat_mma_t(
        const __nv_bfloat16* __restrict__ Ah_g, const __nv_bfloat16* __restrict__ Al_g,
        const __nv_bfloat16* __restrict__ rfh, const __nv_bfloat16* __restrict__ rfl,
        float* __restrict__ outF,
        __nv_bfloat16* __restrict__ outH, __nv_bfloat16* __restrict__ outL) {
    extern __shared__ __nv_bfloat16 sm[];
    uint32_t sbase = smem_u32(sm);
    uint32_t sAh_b = sbase, sAl_b = sbase + FSM_A;
    uint32_t sBh_b = sbase + 2*FSM_A, sBl_b = sbase + 2*FSM_A + FSM_B;
    int t = threadIdx.x, lane = t & 31, w = t >> 5;
    size_t m0 = (size_t)blockIdx.x * 128;

    #pragma unroll
    for (int j = 0; j < 4; j++) {
        int idx = t + j*256;
        int row = idx >> 3, c8 = idx & 7;
        uint32_t off = (uint32_t)(row*AST + c8*8)*2;
        cpa16(sAh_b + off, Ah_g + (m0+row)*KD_ + c8*8);
        cpa16(sAl_b + off, Al_g + (m0+row)*KD_ + c8*8);
    }
    #pragma unroll
    for (int j = 0; j < 8; j++) {
        int idx = t + j*256;
        int row = idx >> 3, c8 = idx & 7;
        uint32_t off = (uint32_t)(row*AST + c8*8)*2;
        cpa16(sBh_b + off, rfh + row*KD_ + c8*8);
        cpa16(sBl_b + off, rfl + row*KD_ + c8*8);
    }
    CPA_COMMIT();
    CPA_WAIT(0);
    __syncthreads();

    float acc[32][4] = {};
    int a_row = w*16 + (lane & 15);
    int a_col8 = (lane >> 4) * 8;
    int b_row = ((lane >> 4) & 1)*8 + (lane & 7);
    int b_col8 = ((lane >> 3) & 1) * 8;

    #pragma unroll
    for (int k16 = 0; k16 < 4; k16++) {
        #pragma unroll
        for (int pass = 0; pass < 3; pass++) {
            uint32_t aBase = (pass == 2) ? sAl_b : sAh_b;
            uint32_t bBase = (pass == 1) ? sBl_b : sBh_b;
            uint32_t aF[4];
            ldsm4(aF[0], aF[1], aF[2], aF[3],
                  aBase + (uint32_t)(a_row*AST + k16*16 + a_col8)*2);
            #pragma unroll
            for (int p = 0; p < 16; p++) {
                uint32_t r0, r1, r2, r3;
                ldsm4(r0, r1, r2, r3,
                      bBase + (uint32_t)((p*16 + b_row)*AST + k16*16 + b_col8)*2);
                uint32_t bf0[2] = {r0, r1}, bf1[2] = {r2, r3};
                mma16816(acc[2*p],   aF, bf0);
                mma16816(acc[2*p+1], aF, bf1);
            }
        }
    }

    int g = lane >> 2;
    float mx0 = -1e30f, mx1 = -1e30f;
    #pragma unroll
    for (int nt = 0; nt < 32; nt++) {
        acc[nt][0] *= SCALE_; acc[nt][1] *= SCALE_;
        acc[nt][2] *= SCALE_; acc[nt][3] *= SCALE_;
        mx0 = fmaxf(mx0, fmaxf(acc[nt][0], acc[nt][1]));
        mx1 = fmaxf(mx1, fmaxf(acc[nt][2], acc[nt][3]));
    }
    mx0 = fmaxf(mx0, __shfl_xor_sync(0xffffffffu, mx0, 1));
    mx0 = fmaxf(mx0, __shfl_xor_sync(0xffffffffu, mx0, 2));
    mx1 = fmaxf(mx1, __shfl_xor_sync(0xffffffffu, mx1, 1));
    mx1 = fmaxf(mx1, __shfl_xor_sync(0xffffffffu, mx1, 2));

    size_t row0 = m0 + w*16 + g;
    int cl = (lane & 3) * 2;
    #pragma unroll
    for (int nt = 0; nt < 32; nt++) {
        int col = nt*8 + cl;
        float v0 = __expf(acc[nt][0]-mx0)+EPS_, v1 = __expf(acc[nt][1]-mx0)+EPS_;
        float v2 = __expf(acc[nt][2]-mx1)+EPS_, v3 = __expf(acc[nt][3]-mx1)+EPS_;
        if (OUTMODE == 0) {
            *(float2*)(outF + row0*R_ + col)     = make_float2(v0, v1);
            *(float2*)(outF + (row0+8)*R_ + col) = make_float2(v2, v3);
        } else {
            __nv_bfloat16 h0,l0,h1,l1,h2,l2,h3,l3;
            split_bf16(v0,h0,l0); split_bf16(v1,h1,l1);
            split_bf16(v2,h2,l2); split_bf16(v3,h3,l3);
            __nv_bfloat162 hp0; hp0.x=h0; hp0.y=h1;
            __nv_bfloat162 lp0; lp0.x=l0; lp0.y=l1;
            __nv_bfloat162 hp1; hp1.x=h2; hp1.y=h3;
            __nv_bfloat162 lp1; lp1.x=l2; lp1.y=l3;
            *(uint32_t*)(outH + row0*R_ + col)     = *(uint32_t*)&hp0;
            *(uint32_t*)(outL + row0*R_ + col)     = *(uint32_t*)&lp0;
            *(uint32_t*)(outH + (row0+8)*R_ + col) = *(uint32_t*)&hp1;
            *(uint32_t*)(outL + (row0+8)*R_ + col) = *(uint32_t*)&lp1;
        }
    }
}

// ---------------- kv partial sums (SIMT, unchanged) ----------------
__global__ void kvsum_kernel(const float* __restrict__ kf, const float* __restrict__ v,
                             float* __restrict__ kvp, float* __restrict__ ksump) {
    __shared__ float kfs[32*256];
    __shared__ float vs[32*64];
    int bh = blockIdx.x, sp = blockIdx.y;
    int b = bh >> 3, h = bh & 7;
    int t = threadIdx.x, tx = t & 15, ty = t >> 4;
    ull acc[8][4] = {};
    float ks = 0.f;
    int sbase = sp*256;
    for (int s0 = 0; s0 < 256; s0 += 32) {
        #pragma unroll
        for (int j = 0; j < 8; j++) {
            int idx = t + 256*j;
            int si = idx >> 6, c = idx & 63;
            size_t row = (size_t)(b*S_ + sbase + s0 + si)*H_ + h;
            ((float4*)kfs)[idx] = ((const float4*)(kf + row*R_))[c];
        }
        #pragma unroll
        for (int j = 0; j < 2; j++) {
            int idx = t + 256*j;
            int si = idx >> 4, c = idx & 15;
            size_t row = (size_t)(b*S_ + sbase + s0 + si)*H_ + h;
            ((float4*)vs)[idx] = ((const float4*)(v + row*KD_))[c];
        }
        __syncthreads();
        for (int si = 0; si < 32; si++) {
            ks += kfs[si*256 + t];
            float4 v4 = ((float4*)(vs + si*64))[tx];
            ull vd[4] = {pk2(v4.x,v4.x), pk2(v4.y,v4.y), pk2(v4.z,v4.z), pk2(v4.w,v4.w)};
            const float2* arow = (const float2*)(kfs + si*256 + ty*16);
            #pragma unroll
            for (int i2 = 0; i2 < 8; i2++) {
                float2 ap = arow[i2];
                ull aa = pk2(ap.x, ap.y);
                #pragma unroll
                for (int j = 0; j < 4; j++)
                    fma2(acc[i2][j], aa, vd[j]);
            }
        }
        __syncthreads();
    }
    size_t base = ((size_t)bh*NSPLIT + sp)*R_;
    ksump[base + t] = ks;
    #pragma unroll
    for (int i2 = 0; i2 < 8; i2++) {
        float2 c0 = up2(acc[i2][0]), c1 = up2(acc[i2][1]);
        float2 c2 = up2(acc[i2][2]), c3 = up2(acc[i2][3]);
        int r0 = ty*16 + 2*i2;
        *(float4*)(kvp + (base + r0)*KD_ + tx*4)     = make_float4(c0.x, c1.x, c2.x, c3.x);
        *(float4*)(kvp + (base + r0 + 1)*KD_ + tx*4) = make_float4(c0.y, c1.y, c2.y, c3.y);
    }
}

// ---------------- reduce -> kvT hi/lo bf16 [bh][80][256]; row64=ksum; 65-79=0 ---------
__global__ void reduce2_kernel(const float* __restrict__ kvp, const float* __restrict__ ksump,
                               __nv_bfloat16* __restrict__ kvth, __nv_bfloat16* __restrict__ kvtl) {
    int idx = blockIdx.x*256 + threadIdx.x;
    const int NKV = B_*H_*KD_*R_;           // 524288
    const int NKS = B_*H_*R_;               // 8192
    if (idx < NKV) {
        int bh = idx >> 14;
        int rem = idx & 16383;
        int d = rem >> 8, r = rem & 255;
        float s = 0.f;
        #pragma unroll
        for (int sp = 0; sp < NSPLIT; sp++)
            s += kvp[((size_t)(bh*NSPLIT + sp) << 14) + r*KD_ + d];
        __nv_bfloat16 h, l; split_bf16(s, h, l);
        size_t o = (size_t)bh*80*R_ + d*R_ + r;
        kvth[o] = h; kvtl[o] = l;
    } else if (idx < NKV + NKS) {
        int j = idx - NKV;
        int bh = j >> 8, r = j & 255;
        float s = 0.f;
        #pragma unroll
        for (int sp = 0; sp < NSPLIT; sp++)
            s += ksump[(bh*NSPLIT + sp)*R_ + r];
        __nv_bfloat16 h, l; split_bf16(s, h, l);
        size_t o = (size_t)bh*80*R_ + 64*R_ + r;
        kvth[o] = h; kvtl[o] = l;
    } else {
        int j = idx - NKV - NKS;             // zero rows 65..79
        if (j < B_*H_*15*R_) {
            int bh = j / (15*R_);
            int rr = j % (15*R_);
            size_t o = (size_t)bh*80*R_ + 65*R_ + rr;
            kvth[o] = __float2bfloat16(0.f);
            kvtl[o] = __float2bfloat16(0.f);
        }
    }
}

// ---------------- attn via HMMA: A=qf hi/lo [bh rows], B=kvT hi/lo [80][256] ----------
// Block: 128 s-rows x 80 cols, K=256 in 4 chunks, double-buffered.
// Output col 64 = den; cols 0-63 = num. Writes attn as bf16 hi/lo into [m][512].
#define ATT_N 80
#define ASM_A (128*AST*2)
#define ASM_B (ATT_N*AST*2)
#define ABUF (2*ASM_A + 2*ASM_B)
#define ATSM (2*ABUF)
__global__ void __launch_bounds__(256) attn_mma(
        const __nv_bfloat16* __restrict__ qfh, const __nv_bfloat16* __restrict__ qfl,
        const __nv_bfloat16* __restrict__ kvth, const __nv_bfloat16* __restrict__ kvtl,
        __nv_bfloat16* __restrict__ Ch, __nv_bfloat16* __restrict__ Cl) {
    extern __shared__ __nv_bfloat16 sm[];
    uint32_t sbase = smem_u32(sm);
    int t = threadIdx.x, lane = t & 31, w = t >> 5;
    int bh = blockIdx.y, b = bh >> 3, h = bh & 7;
    int s0 = blockIdx.x * 128;

    const __nv_bfloat16* Bh_g = kvth + (size_t)bh*ATT_N*R_;
    const __nv_bfloat16* Bl_g = kvtl + (size_t)bh*ATT_N*R_;

    float acc[10][4] = {};

    int a_row = w*16 + (lane & 15);
    int a_col8 = (lane >> 4) * 8;
    int b_row = ((lane >> 4) & 1)*8 + (lane & 7);
    int b_col8 = ((lane >> 3) & 1) * 8;

    // stage helper: chunk kc into buffer buf
    auto stage = [&](int kc, int buf) {
        uint32_t bb = sbase + buf*ABUF;
        #pragma unroll
        for (int j = 0; j < 4; j++) {
            int idx = t + j*256;                 // 0..1023 -> A rows
            int row = idx >> 3, c8 = idx & 7;
            size_t g = ((size_t)(b*S_ + s0 + row)*H_ + h)*R_ + kc*64 + c8*8;
            uint32_t off = (uint32_t)(row*AST + c8*8)*2;
            cpa16(bb + off,          qfh + g);
            cpa16(bb + ASM_A + off,  qfl + g);
        }
        #pragma unroll
        for (int j = 0; j < 3; j++) {
            int idx = t + j*256;                 // need 0..639
            if (idx < ATT_N*8) {
                int row = idx >> 3, c8 = idx & 7;
                uint32_t off = (uint32_t)(row*AST + c8*8)*2;
                cpa16(bb + 2*ASM_A + off,          Bh_g + row*R_ + kc*64 + c8*8);
                cpa16(bb + 2*ASM_A + ASM_B + off,  Bl_g + row*R_ + kc*64 + c8*8);
            }
        }
        CPA_COMMIT();
    };

    stage(0, 0);
    for (int c = 0; c < 4; c++) {
        int buf = c & 1;
        if (c < 3) {
            stage(c+1, buf^1);
            CPA_WAIT(1);
        } else {
            CPA_WAIT(0);
        }
        __syncthreads();

        uint32_t bb = sbase + buf*ABUF;
        uint32_t sAh_b = bb, sAl_b = bb + ASM_A;
        uint32_t sBh_b = bb + 2*ASM_A, sBl_b = bb + 2*ASM_A + ASM_B;

        #pragma unroll
        for (int k16 = 0; k16 < 4; k16++) {
            #pragma unroll
            for (int pass = 0; pass < 3; pass++) {
                uint32_t aBase = (pass == 2) ? sAl_b : sAh_b;
                uint32_t bBase = (pass == 1) ? sBl_b : sBh_b;
                uint32_t aF[4];
                ldsm4(aF[0], aF[1], aF[2], aF[3],
                      aBase + (uint32_t)(a_row*AST + k16*16 + a_col8)*2);
                #pragma unroll
                for (int p = 0; p < 5; p++) {
                    uint32_t r0, r1, r2, r3;
                    ldsm4(r0, r1, r2, r3,
                          bBase + (uint32_t)((p*16 + b_row)*AST + k16*16 + b_col8)*2);
                    uint32_t bf0[2] = {r0, r1}, bf1[2] = {r2, r3};
                    mma16816(acc[2*p],   aF, bf0);
                    mma16816(acc[2*p+1], aF, bf1);
                }
            }
        }
        __syncthreads();
    }

    // epilogue: den = col 64 (nt=8, cl=0), quad-broadcast, divide, write hi/lo
    int g = lane >> 2;
    int cl = (lane & 3) * 2;
    float den0 = __shfl_sync(0xffffffffu, acc[8][0], lane & ~3);
    float den1 = __shfl_sync(0xffffffffu, acc[8][2], lane & ~3);
    float inv0 = 1.0f / (den0 + EPS_);
    float inv1 = 1.0f / (den1 + EPS_);

    size_t srow0 = (size_t)(b*S_ + s0 + w*16 + g);
    #pragma unroll
    for (int nt = 0; nt < 8; nt++) {
        int col = h*KD_ + nt*8 + cl;
        float v0 = acc[nt][0]*inv0, v1 = acc[nt][1]*inv0;
        float v2 = acc[nt][2]*inv1, v3 = acc[nt][3]*inv1;
        __nv_bfloat16 h0,l0,h1,l1,h2,l2,h3,l3;
        split_bf16(v0,h0,l0); split_bf16(v1,h1,l1);
        split_bf16(v2,h2,l2); split_bf16(v3,h3,l3);
        __nv_bfloat162 hp0; hp0.x=h0; hp0.y=h1;
        __nv_bfloat162 lp0; lp0.x=l0; lp0.y=l1;
        __nv_bfloat162 hp1; hp1.x=h2; hp1.y=h3;
        __nv_bfloat162 lp1; lp1.x=l2; lp1.y=l3;
        *(uint32_t*)(Ch + srow0*D_ + col)     = *(uint32_t*)&hp0;
        *(uint32_t*)(Cl + srow0*D_ + col)     = *(uint32_t*)&lp0;
        *(uint32_t*)(Ch + (srow0+8)*D_ + col) = *(uint32_t*)&hp1;
        *(uint32_t*)(Cl + (srow0+8)*D_ + col) = *(uint32_t*)&lp1;
    }
}

// ---------------- launch ----------------
extern "C" void kernel_launch(void* const* d_in, const int* in_sizes, int n_in,
                              void* d_out, int out_size) {
    const float* x  = (const float*)d_in[0];
    const float* Wq = (const float*)d_in[1];
    const float* Wk = (const float*)d_in[2];
    const float* Wv = (const float*)d_in[3];
    const float* rf = (const float*)d_in[4];
    const float* Wo = (const float*)d_in[5];
    const float* bo = (const float*)d_in[6];
    float* out = (float*)d_out;

    float *pv, *pkf, *pkvp, *pksp;
    __nv_bfloat16 *pxh, *pxl, *pah, *pal, *pqh, *pql, *pkh, *pkl, *prfh, *prfl, *pwh, *pwl;
    __nv_bfloat16 *pqfh, *pqfl, *pkvth, *pkvtl;
    cudaGetSymbolAddress((void**)&pv,    g_v);
    cudaGetSymbolAddress((void**)&pkf,   g_kf);
    cudaGetSymbolAddress((void**)&pkvp,  g_kvp);
    cudaGetSymbolAddress((void**)&pksp,  g_ksump);
    cudaGetSymbolAddress((void**)&pxh,   g_xh);
    cudaGetSymbolAddress((void**)&pxl,   g_xl);
    cudaGetSymbolAddress((void**)&pah,   g_ah);
    cudaGetSymbolAddress((void**)&pal,   g_al);
    cudaGetSymbolAddress((void**)&pqh,   g_qh);
    cudaGetSymbolAddress((void**)&pql,   g_ql);
    cudaGetSymbolAddress((void**)&pkh,   g_kh);
    cudaGetSymbolAddress((void**)&pkl,   g_kl);
    cudaGetSymbolAddress((void**)&prfh,  g_rfh);
    cudaGetSymbolAddress((void**)&prfl,  g_rfl);
    cudaGetSymbolAddress((void**)&pwh,   g_wh);
    cudaGetSymbolAddress((void**)&pwl,   g_wl);
    cudaGetSymbolAddress((void**)&pqfh,  g_qfh);
    cudaGetSymbolAddress((void**)&pqfl,  g_qfl);
    cudaGetSymbolAddress((void**)&pkvth, g_kvth);
    cudaGetSymbolAddress((void**)&pkvtl, g_kvtl);

    cudaFuncSetAttribute(mma_gemm_t<0>, cudaFuncAttributeMaxDynamicSharedMemorySize, MMSM);
    cudaFuncSetAttribute(mma_gemm_t<1>, cudaFuncAttributeMaxDynamicSharedMemorySize, MMSM);
    cudaFuncSetAttribute(feat_mma_t<0>, cudaFuncAttributeMaxDynamicSharedMemorySize, FSM_TOT);
    cudaFuncSetAttribute(feat_mma_t<1>, cudaFuncAttributeMaxDynamicSharedMemorySize, FSM_TOT);
    cudaFuncSetAttribute(attn_mma,      cudaFuncAttributeMaxDynamicSharedMemorySize, ATSM);

    const int WSZ = D_*D_;
    wsplit_all<<<dim3(16, 16, 4), dim3(32, 8)>>>(Wq, Wk, Wv, Wo, pwh, pwl);

    split_kernel<<<M_*D_/4/256, 256>>>((const float4*)x, (uint2*)pxh, (uint2*)pxl);
    split_kernel<<<R_*KD_/4/256, 256>>>((const float4*)rf, (uint2*)prfh, (uint2*)prfl);

    dim3 tg(D_/128, M_/128);   // (4, 128)
    mma_gemm_t<1><<<tg, 256, MMSM>>>(pxh, pxl, pwh + 0*WSZ, pwl + 0*WSZ, nullptr, nullptr, pqh, pql);
    mma_gemm_t<1><<<tg, 256, MMSM>>>(pxh, pxl, pwh + 1*WSZ, pwl + 1*WSZ, nullptr, nullptr, pkh, pkl);
    mma_gemm_t<0><<<tg, 256, MMSM>>>(pxh, pxl, pwh + 2*WSZ, pwl + 2*WSZ, pv, nullptr, nullptr, nullptr);

    feat_mma_t<1><<<ROWS_/128, 256, FSM_TOT>>>(pqh, pql, prfh, prfl, nullptr, pqfh, pqfl);
    feat_mma_t<0><<<ROWS_/128, 256, FSM_TOT>>>(pkh, pkl, prfh, prfl, pkf, nullptr, nullptr);

    kvsum_kernel<<<dim3(B_*H_, NSPLIT), 256>>>(pkf, pv, pkvp, pksp);

    const int NRED = B_*H_*KD_*R_ + B_*H_*R_ + B_*H_*15*R_;
    reduce2_kernel<<<(NRED + 255)/256, 256>>>(pkvp, pksp, pkvth, pkvtl);

    attn_mma<<<dim3(S_/128, B_*H_), 256, ATSM>>>(pqfh, pqfl, pkvth, pkvtl, pah, pal);

    mma_gemm_t<0><<<tg, 256, MMSM>>>(pah, pal, pwh + 3*WSZ, pwl + 3*WSZ, out, bo, nullptr, nullptr);
}